// round 1
// baseline (speedup 1.0000x reference)
#include <cuda_runtime.h>
#include <math.h>

#define SEQ 1024
#define EMB 1024
#define BSZ 4
#define NH  16
#define HD  64
#define SCALING 0.125f
#define ATTN_CONST 3.032639477052158f

// ---------------- scratch (device globals; no allocations allowed) ----------
__device__ float g_q[BSZ * SEQ * EMB];
__device__ float g_k[BSZ * SEQ * EMB];
__device__ float g_v[BSZ * SEQ * EMB];
__device__ float g_attn[BSZ * SEQ * EMB];
__device__ float g_scores[67108864]; // BSZ*NH*SEQ*SEQ = 64M floats = 256MB

// ---------------- 128x128x16 NT SGEMM: C = (A*B^T + bias)*scale -------------
// A: MxK row-major (lda), B: NxK row-major (ldb), bias per-column n.
__global__ __launch_bounds__(256)
void gemm_nt128(const float* __restrict__ A, const float* __restrict__ B,
                const float* __restrict__ bias, float* __restrict__ C,
                int lda, int ldb, int ldc, int K, float scale)
{
    __shared__ float As[16][128];
    __shared__ float Bs[16][128];
    const int tid = threadIdx.x;
    const int tx = tid & 15, ty = tid >> 4;
    const int m0 = blockIdx.y * 128, n0 = blockIdx.x * 128;

    float acc[8][8];
#pragma unroll
    for (int i = 0; i < 8; i++)
#pragma unroll
        for (int j = 0; j < 8; j++) acc[i][j] = 0.f;

    for (int kk = 0; kk < K; kk += 16) {
#pragma unroll
        for (int i = 0; i < 2; i++) {
            int e = tid + i * 256;          // 512 float4 per tile
            int r = e >> 2;
            int c = (e & 3) << 2;
            float4 va = *(const float4*)(A + (size_t)(m0 + r) * lda + kk + c);
            As[c + 0][r] = va.x; As[c + 1][r] = va.y;
            As[c + 2][r] = va.z; As[c + 3][r] = va.w;
            float4 vb = *(const float4*)(B + (size_t)(n0 + r) * ldb + kk + c);
            Bs[c + 0][r] = vb.x; Bs[c + 1][r] = vb.y;
            Bs[c + 2][r] = vb.z; Bs[c + 3][r] = vb.w;
        }
        __syncthreads();
#pragma unroll
        for (int k = 0; k < 16; k++) {
            float4 a0 = *(const float4*)&As[k][ty * 8];
            float4 a1 = *(const float4*)&As[k][ty * 8 + 4];
            float4 b0 = *(const float4*)&Bs[k][tx * 8];
            float4 b1 = *(const float4*)&Bs[k][tx * 8 + 4];
            float a[8] = {a0.x, a0.y, a0.z, a0.w, a1.x, a1.y, a1.z, a1.w};
            float b[8] = {b0.x, b0.y, b0.z, b0.w, b1.x, b1.y, b1.z, b1.w};
#pragma unroll
            for (int i = 0; i < 8; i++)
#pragma unroll
                for (int j = 0; j < 8; j++) acc[i][j] += a[i] * b[j];
        }
        __syncthreads();
    }

#pragma unroll
    for (int i = 0; i < 8; i++) {
        int m = m0 + ty * 8 + i;
#pragma unroll
        for (int j = 0; j < 8; j += 4) {
            int n = n0 + tx * 8 + j;
            float4 bv = *(const float4*)(bias + n);
            float4 o;
            o.x = (acc[i][j + 0] + bv.x) * scale;
            o.y = (acc[i][j + 1] + bv.y) * scale;
            o.z = (acc[i][j + 2] + bv.z) * scale;
            o.w = (acc[i][j + 3] + bv.w) * scale;
            *(float4*)(C + (size_t)m * ldc + n) = o;
        }
    }
}

// ---------------- scores: S[bh,t,s] = q·k^T + ATTN_CONST*bias  (K=64) -------
__global__ __launch_bounds__(256)
void scores128(const float* __restrict__ Q, const float* __restrict__ Kmat,
               const float* __restrict__ biasmat, float* __restrict__ S)
{
    __shared__ float As[16][128];
    __shared__ float Bs[16][128];
    const int tid = threadIdx.x;
    const int tx = tid & 15, ty = tid >> 4;
    const int bh = blockIdx.z, b = bh >> 4, h = bh & 15;
    const float* A = Q    + (size_t)b * SEQ * EMB + h * HD;
    const float* B = Kmat + (size_t)b * SEQ * EMB + h * HD;
    const size_t sbase = (size_t)bh * SEQ * SEQ;
    const int m0 = blockIdx.y * 128, n0 = blockIdx.x * 128;

    float acc[8][8];
#pragma unroll
    for (int i = 0; i < 8; i++)
#pragma unroll
        for (int j = 0; j < 8; j++) acc[i][j] = 0.f;

    for (int kk = 0; kk < HD; kk += 16) {
#pragma unroll
        for (int i = 0; i < 2; i++) {
            int e = tid + i * 256;
            int r = e >> 2;
            int c = (e & 3) << 2;
            float4 va = *(const float4*)(A + (size_t)(m0 + r) * EMB + kk + c);
            As[c + 0][r] = va.x; As[c + 1][r] = va.y;
            As[c + 2][r] = va.z; As[c + 3][r] = va.w;
            float4 vb = *(const float4*)(B + (size_t)(n0 + r) * EMB + kk + c);
            Bs[c + 0][r] = vb.x; Bs[c + 1][r] = vb.y;
            Bs[c + 2][r] = vb.z; Bs[c + 3][r] = vb.w;
        }
        __syncthreads();
#pragma unroll
        for (int k = 0; k < 16; k++) {
            float4 a0 = *(const float4*)&As[k][ty * 8];
            float4 a1 = *(const float4*)&As[k][ty * 8 + 4];
            float4 b0 = *(const float4*)&Bs[k][tx * 8];
            float4 b1 = *(const float4*)&Bs[k][tx * 8 + 4];
            float a[8] = {a0.x, a0.y, a0.z, a0.w, a1.x, a1.y, a1.z, a1.w};
            float b[8] = {b0.x, b0.y, b0.z, b0.w, b1.x, b1.y, b1.z, b1.w};
#pragma unroll
            for (int i = 0; i < 8; i++)
#pragma unroll
                for (int j = 0; j < 8; j++) acc[i][j] += a[i] * b[j];
        }
        __syncthreads();
    }

#pragma unroll
    for (int i = 0; i < 8; i++) {
        int m = m0 + ty * 8 + i;
#pragma unroll
        for (int j = 0; j < 8; j += 4) {
            int n = n0 + tx * 8 + j;
            size_t idx = sbase + (size_t)m * SEQ + n;
            float4 bb = *(const float4*)(biasmat + idx);
            float4 o;
            o.x = acc[i][j + 0] + ATTN_CONST * bb.x;
            o.y = acc[i][j + 1] + ATTN_CONST * bb.y;
            o.z = acc[i][j + 2] + ATTN_CONST * bb.z;
            o.w = acc[i][j + 3] + ATTN_CONST * bb.w;
            *(float4*)(S + idx) = o;
        }
    }
}

// ---------------- row softmax over 1024 elements, in place ------------------
__global__ __launch_bounds__(256)
void softmax_rows(float* __restrict__ S)
{
    const size_t row = blockIdx.x;
    float4* p = (float4*)(S + row * SEQ);
    const int t = threadIdx.x;
    const int w = t >> 5, l = t & 31;
    __shared__ float ra[8], rb[8];

    float4 v = p[t];
    float m = fmaxf(fmaxf(v.x, v.y), fmaxf(v.z, v.w));
#pragma unroll
    for (int o = 16; o > 0; o >>= 1) m = fmaxf(m, __shfl_xor_sync(0xffffffffu, m, o));
    if (l == 0) ra[w] = m;
    __syncthreads();
    if (t == 0) {
        float x = ra[0];
#pragma unroll
        for (int i = 1; i < 8; i++) x = fmaxf(x, ra[i]);
        ra[0] = x;
    }
    __syncthreads();
    m = ra[0];

    v.x = __expf(v.x - m); v.y = __expf(v.y - m);
    v.z = __expf(v.z - m); v.w = __expf(v.w - m);
    float s = v.x + v.y + v.z + v.w;
#pragma unroll
    for (int o = 16; o > 0; o >>= 1) s += __shfl_xor_sync(0xffffffffu, s, o);
    if (l == 0) rb[w] = s;
    __syncthreads();
    if (t == 0) {
        float x = 0.f;
#pragma unroll
        for (int i = 0; i < 8; i++) x += rb[i];
        rb[0] = x;
    }
    __syncthreads();
    float inv = 1.0f / rb[0];
    v.x *= inv; v.y *= inv; v.z *= inv; v.w *= inv;
    p[t] = v;
}

// ---------------- AV: out[b,t,h*64+d] = sum_s P[bh,t,s] * v[b,s,h*64+d] -----
// 64x64 tile, BK=32, NN GEMM (A row-major, B row-major K x N).
__global__ __launch_bounds__(256)
void av64(const float* __restrict__ P, const float* __restrict__ V,
          float* __restrict__ O)
{
    __shared__ float As[32][64];
    __shared__ float Bs[32][64];
    const int tid = threadIdx.x;
    const int tx = tid & 15, ty = tid >> 4;
    const int bh = blockIdx.z, b = bh >> 4, h = bh & 15;
    const float* Ap = P + (size_t)bh * SEQ * SEQ;           // lda = SEQ
    const float* Bp = V + (size_t)b * SEQ * EMB + h * HD;   // ldb = EMB
    float*       Cp = O + (size_t)b * SEQ * EMB + h * HD;   // ldc = EMB
    const int m0 = blockIdx.y * 64;

    float acc[4][4];
#pragma unroll
    for (int i = 0; i < 4; i++)
#pragma unroll
        for (int j = 0; j < 4; j++) acc[i][j] = 0.f;

    for (int kk = 0; kk < SEQ; kk += 32) {
#pragma unroll
        for (int i = 0; i < 2; i++) {
            int e = tid + i * 256;              // 512 float4: A tile 64x32
            int r = e >> 3;
            int c = (e & 7) << 2;
            float4 va = *(const float4*)(Ap + (size_t)(m0 + r) * SEQ + kk + c);
            As[c + 0][r] = va.x; As[c + 1][r] = va.y;
            As[c + 2][r] = va.z; As[c + 3][r] = va.w;
            int rb = e >> 4;                    // B tile 32x64
            int cb = (e & 15) << 2;
            float4 vb = *(const float4*)(Bp + (size_t)(kk + rb) * EMB + cb);
            *(float4*)&Bs[rb][cb] = vb;
        }
        __syncthreads();
#pragma unroll
        for (int k = 0; k < 32; k++) {
            float4 a4 = *(const float4*)&As[k][ty * 4];
            float4 b4 = *(const float4*)&Bs[k][tx * 4];
            float a[4] = {a4.x, a4.y, a4.z, a4.w};
            float bb[4] = {b4.x, b4.y, b4.z, b4.w};
#pragma unroll
            for (int i = 0; i < 4; i++)
#pragma unroll
                for (int j = 0; j < 4; j++) acc[i][j] += a[i] * bb[j];
        }
        __syncthreads();
    }

#pragma unroll
    for (int i = 0; i < 4; i++) {
        int m = m0 + ty * 4 + i;
        float4 o = make_float4(acc[i][0], acc[i][1], acc[i][2], acc[i][3]);
        *(float4*)(Cp + (size_t)m * EMB + tx * 4) = o;
    }
}

// ---------------- launcher ---------------------------------------------------
extern "C" void kernel_launch(void* const* d_in, const int* in_sizes, int n_in,
                              void* d_out, int out_size)
{
    const float* hidden = (const float*)d_in[0];
    const float* attn_b = (const float*)d_in[1];
    const float* Wq = (const float*)d_in[2];
    const float* bq = (const float*)d_in[3];
    const float* Wk = (const float*)d_in[4];
    const float* bk = (const float*)d_in[5];
    const float* Wv = (const float*)d_in[6];
    const float* bv = (const float*)d_in[7];
    const float* Wo = (const float*)d_in[8];
    const float* bo = (const float*)d_in[9];
    float* out = (float*)d_out;

    float *qp, *kp, *vp, *ap, *sp;
    cudaGetSymbolAddress((void**)&qp, g_q);
    cudaGetSymbolAddress((void**)&kp, g_k);
    cudaGetSymbolAddress((void**)&vp, g_v);
    cudaGetSymbolAddress((void**)&ap, g_attn);
    cudaGetSymbolAddress((void**)&sp, g_scores);

    dim3 gproj(EMB / 128, (BSZ * SEQ) / 128);      // (8, 32)

    // QKV projections (q pre-scaled by SCALING)
    gemm_nt128<<<gproj, 256>>>(hidden, Wq, bq, qp, EMB, EMB, EMB, EMB, SCALING);
    gemm_nt128<<<gproj, 256>>>(hidden, Wk, bk, kp, EMB, EMB, EMB, EMB, 1.0f);
    gemm_nt128<<<gproj, 256>>>(hidden, Wv, bv, vp, EMB, EMB, EMB, EMB, 1.0f);

    // scores + additive bias
    scores128<<<dim3(SEQ / 128, SEQ / 128, BSZ * NH), 256>>>(qp, kp, attn_b, sp);

    // softmax (one block per row)
    softmax_rows<<<BSZ * NH * SEQ, 256>>>(sp);

    // attn @ V
    av64<<<dim3(1, SEQ / 64, BSZ * NH), 256>>>(sp, vp, ap);

    // output projection
    gemm_nt128<<<gproj, 256>>>(ap, Wo, bo, out, EMB, EMB, EMB, EMB, 1.0f);
}

// round 3
// speedup vs baseline: 1.9581x; 1.9581x over previous
#include <cuda_runtime.h>
#include <cstdint>
#include <math.h>

#define SEQ 1024
#define EMB 1024
#define BSZ 4
#define NH  16
#define HD  64
#define SCALING 0.125f
#define ATTN_CONST 3.032639477052158f

// ---------------- scratch (device globals; no allocations allowed) ----------
__device__ float g_q[BSZ * SEQ * EMB];
__device__ float g_k[BSZ * SEQ * EMB];
__device__ float g_v[BSZ * SEQ * EMB];
__device__ float g_attn[BSZ * SEQ * EMB];
__device__ float g_scores[67108864];          // BSZ*NH*SEQ*SEQ floats = 256MB

__device__ __forceinline__ uint32_t f2tf(float x) {
    uint32_t r;
    asm("cvt.rna.tf32.f32 %0, %1;" : "=r"(r) : "f"(x));
    return r;
}
__device__ __forceinline__ uint4 cvt4(float4 v) {
    uint4 t;
    t.x = f2tf(v.x); t.y = f2tf(v.y); t.z = f2tf(v.z); t.w = f2tf(v.w);
    return t;
}
__device__ __forceinline__ void mma_tf32(float* c, const uint32_t* a, const uint32_t* b) {
    asm volatile(
        "mma.sync.aligned.m16n8k8.row.col.f32.tf32.tf32.f32 "
        "{%0,%1,%2,%3}, {%4,%5,%6,%7}, {%8,%9}, {%0,%1,%2,%3};"
        : "+f"(c[0]), "+f"(c[1]), "+f"(c[2]), "+f"(c[3])
        : "r"(a[0]), "r"(a[1]), "r"(a[2]), "r"(a[3]), "r"(b[0]), "r"(b[1]));
}

// ============ tf32 mma.sync GEMM ============================================
// C[m,n] = f( sum_k A[m,k] * B(k,n) )
// MODE 0 (proj):  B row-major NxK (weights). C=(acc+bias[n])*scale.
// MODE 2 (scores): per-z head slices; B=K-matrix NxK. C=acc+ATTN_CONST*biasmat.
// MODE 3 (AV):    B row-major KxN (V natural layout). plain store.
// Block tile: 128 x BN, BK=16, 256 threads (8 warps).
template <int BN, int MODE>
__global__ void __launch_bounds__(256, 1)
mma_gemm(const float* __restrict__ A, const float* __restrict__ B,
         const float* __restrict__ bias, const float* __restrict__ biasmat,
         float* __restrict__ C, int K, int lda, int ldb, int ldc, float scale)
{
    constexpr int BM = 128, BK = 16;
    constexpr bool BNN = (MODE == 3);          // B is KxN row-major
    constexpr int WROWS = (BN == 128) ? 2 : 4; // warps along M
    constexpr int WCOLS = 8 / WROWS;           // warps along N
    constexpr int WM = BM / WROWS;             // 64 or 32
    constexpr int WN = BN / WCOLS;             // 32
    constexpr int MI = WM / 16;                // 4 or 2
    constexpr int NI = WN / 8;                 // 4

    __shared__ uint32_t As[2][BM][BK + 4];                     // stride 20
    __shared__ uint32_t Bs[2][BNN ? BK : BN][BNN ? BN + 8 : BK + 4];

    const int tid = threadIdx.x;
    const int wid = tid >> 5, lane = tid & 31;
    const int lq = lane >> 2, lr = lane & 3;
    const int warp_m = (wid % WROWS) * WM;
    const int warp_n = (wid / WROWS) * WN;
    const int m0 = blockIdx.y * BM;
    const int n0 = blockIdx.x * BN;
    const int bz = blockIdx.z;

    const float* Abase = A;
    const float* Bbase = B;
    float* Cbase = C;
    const float* BM2 = biasmat;
    if (MODE == 2) {
        int b = bz >> 4, h = bz & 15;
        Abase += (size_t)b * SEQ * EMB + h * HD;
        Bbase += (size_t)b * SEQ * EMB + h * HD;
        Cbase += (size_t)bz * SEQ * SEQ;
        BM2   += (size_t)bz * SEQ * SEQ;
    } else if (MODE == 3) {
        Abase += (size_t)bz * SEQ * SEQ;
        Bbase += (size_t)(bz >> 4) * SEQ * EMB + (bz & 15) * HD;
        Cbase += (size_t)(bz >> 4) * SEQ * EMB + (bz & 15) * HD;
    }

    float acc[MI][NI][4];
#pragma unroll
    for (int mi = 0; mi < MI; mi++)
#pragma unroll
        for (int ni = 0; ni < NI; ni++)
#pragma unroll
            for (int j = 0; j < 4; j++) acc[mi][ni][j] = 0.f;

    const int nk = K / BK;

    // -------- global load helpers (into registers) --------
    float4 pa[2], pb[2];
    auto ldg_tile = [&](int kk) {
        const float* Ag = Abase + (size_t)m0 * lda + kk * BK;
#pragma unroll
        for (int i = 0; i < 2; i++) {
            int e = tid + (i << 8);
            int r = e >> 2, c = (e & 3) << 2;
            pa[i] = *(const float4*)(Ag + (size_t)r * lda + c);
        }
        if (!BNN) {
            const float* Bg = Bbase + (size_t)n0 * ldb + kk * BK;
#pragma unroll
            for (int i = 0; i < (BN == 128 ? 2 : 1); i++) {
                int e = tid + (i << 8);
                int r = e >> 2, c = (e & 3) << 2;
                pb[i] = *(const float4*)(Bg + (size_t)r * ldb + c);
            }
        } else {
            const float* Bg = Bbase + (size_t)(kk * BK) * ldb;  // rows k, cols n
            int r = tid >> 4, c = (tid & 15) << 2;
            pb[0] = *(const float4*)(Bg + (size_t)r * ldb + c);
        }
    };
    auto sts_tile = [&](int buf) {
#pragma unroll
        for (int i = 0; i < 2; i++) {
            int e = tid + (i << 8);
            int r = e >> 2, c = (e & 3) << 2;
            *(uint4*)&As[buf][r][c] = cvt4(pa[i]);
        }
        if (!BNN) {
#pragma unroll
            for (int i = 0; i < (BN == 128 ? 2 : 1); i++) {
                int e = tid + (i << 8);
                int r = e >> 2, c = (e & 3) << 2;
                *(uint4*)&Bs[buf][r][c] = cvt4(pb[i]);
            }
        } else {
            int r = tid >> 4, c = (tid & 15) << 2;
            *(uint4*)&Bs[buf][r][c] = cvt4(pb[0]);
        }
    };
    auto compute = [&](int buf) {
#pragma unroll
        for (int ks = 0; ks < 2; ks++) {
            const int k0 = ks * 8 + lr;
            uint32_t af[MI][4];
#pragma unroll
            for (int mi = 0; mi < MI; mi++) {
                int row = warp_m + mi * 16 + lq;
                af[mi][0] = As[buf][row][k0];
                af[mi][1] = As[buf][row + 8][k0];
                af[mi][2] = As[buf][row][k0 + 4];
                af[mi][3] = As[buf][row + 8][k0 + 4];
            }
            uint32_t bf[NI][2];
#pragma unroll
            for (int ni = 0; ni < NI; ni++) {
                int n = warp_n + ni * 8 + lq;
                if (!BNN) {
                    bf[ni][0] = Bs[buf][n][k0];
                    bf[ni][1] = Bs[buf][n][k0 + 4];
                } else {
                    bf[ni][0] = Bs[buf][k0][n];
                    bf[ni][1] = Bs[buf][k0 + 4][n];
                }
            }
#pragma unroll
            for (int mi = 0; mi < MI; mi++)
#pragma unroll
                for (int ni = 0; ni < NI; ni++)
                    mma_tf32(acc[mi][ni], af[mi], bf[ni]);
        }
    };

    // -------- pipelined main loop --------
    ldg_tile(0);
    sts_tile(0);
    __syncthreads();
    for (int kk = 0; kk < nk; kk++) {
        if (kk + 1 < nk) ldg_tile(kk + 1);
        compute(kk & 1);
        if (kk + 1 < nk) sts_tile((kk + 1) & 1);
        __syncthreads();
    }

    // -------- epilogue --------
#pragma unroll
    for (int mi = 0; mi < MI; mi++) {
#pragma unroll
        for (int ni = 0; ni < NI; ni++) {
            int row = m0 + warp_m + mi * 16 + lq;
            int col = n0 + warp_n + ni * 8 + (lr << 1);
#pragma unroll
            for (int h = 0; h < 2; h++) {
                int r = row + h * 8;
                float x = acc[mi][ni][h * 2 + 0];
                float y = acc[mi][ni][h * 2 + 1];
                if (MODE == 0) {
                    float2 bv = *(const float2*)(bias + col);
                    float2 o = make_float2((x + bv.x) * scale, (y + bv.y) * scale);
                    *(float2*)(Cbase + (size_t)r * ldc + col) = o;
                } else if (MODE == 2) {
                    size_t idx = (size_t)r * SEQ + col;
                    float2 bv = *(const float2*)(BM2 + idx);
                    float2 o = make_float2(x + ATTN_CONST * bv.x, y + ATTN_CONST * bv.y);
                    *(float2*)(Cbase + idx) = o;
                } else {
                    *(float2*)(Cbase + (size_t)r * ldc + col) = make_float2(x, y);
                }
            }
        }
    }
}

// ---------------- row softmax over 1024 elements, in place ------------------
__global__ __launch_bounds__(256)
void softmax_rows(float* __restrict__ S)
{
    const size_t row = blockIdx.x;
    float4* p = (float4*)(S + row * SEQ);
    const int t = threadIdx.x;
    const int w = t >> 5, l = t & 31;
    __shared__ float ra[8], rb[8];

    float4 v = p[t];
    float m = fmaxf(fmaxf(v.x, v.y), fmaxf(v.z, v.w));
#pragma unroll
    for (int o = 16; o > 0; o >>= 1) m = fmaxf(m, __shfl_xor_sync(0xffffffffu, m, o));
    if (l == 0) ra[w] = m;
    __syncthreads();
    if (t == 0) {
        float x = ra[0];
#pragma unroll
        for (int i = 1; i < 8; i++) x = fmaxf(x, ra[i]);
        ra[0] = x;
    }
    __syncthreads();
    m = ra[0];

    v.x = __expf(v.x - m); v.y = __expf(v.y - m);
    v.z = __expf(v.z - m); v.w = __expf(v.w - m);
    float s = v.x + v.y + v.z + v.w;
#pragma unroll
    for (int o = 16; o > 0; o >>= 1) s += __shfl_xor_sync(0xffffffffu, s, o);
    if (l == 0) rb[w] = s;
    __syncthreads();
    if (t == 0) {
        float x = 0.f;
#pragma unroll
        for (int i = 0; i < 8; i++) x += rb[i];
        rb[0] = x;
    }
    __syncthreads();
    float inv = 1.0f / rb[0];
    v.x *= inv; v.y *= inv; v.z *= inv; v.w *= inv;
    p[t] = v;
}

// ---------------- launcher ---------------------------------------------------
extern "C" void kernel_launch(void* const* d_in, const int* in_sizes, int n_in,
                              void* d_out, int out_size)
{
    const float* hidden = (const float*)d_in[0];
    const float* attn_b = (const float*)d_in[1];
    const float* Wq = (const float*)d_in[2];
    const float* bq = (const float*)d_in[3];
    const float* Wk = (const float*)d_in[4];
    const float* bk = (const float*)d_in[5];
    const float* Wv = (const float*)d_in[6];
    const float* bv = (const float*)d_in[7];
    const float* Wo = (const float*)d_in[8];
    const float* bo = (const float*)d_in[9];
    float* out = (float*)d_out;

    float *qp, *kp, *vp, *ap, *sp;
    cudaGetSymbolAddress((void**)&qp, g_q);
    cudaGetSymbolAddress((void**)&kp, g_k);
    cudaGetSymbolAddress((void**)&vp, g_v);
    cudaGetSymbolAddress((void**)&ap, g_attn);
    cudaGetSymbolAddress((void**)&sp, g_scores);

    dim3 gproj(EMB / 128, (BSZ * SEQ) / 128, 1);   // (8, 32)

    // QKV projections (q pre-scaled by SCALING)
    mma_gemm<128, 0><<<gproj, 256>>>(hidden, Wq, bq, nullptr, qp,
                                     EMB, EMB, EMB, EMB, SCALING);
    mma_gemm<128, 0><<<gproj, 256>>>(hidden, Wk, bk, nullptr, kp,
                                     EMB, EMB, EMB, EMB, 1.0f);
    mma_gemm<128, 0><<<gproj, 256>>>(hidden, Wv, bv, nullptr, vp,
                                     EMB, EMB, EMB, EMB, 1.0f);

    // scores = q @ k^T + ATTN_CONST * bias
    mma_gemm<128, 2><<<dim3(SEQ / 128, SEQ / 128, BSZ * NH), 256>>>(
        qp, kp, nullptr, attn_b, sp, HD, EMB, EMB, SEQ, 1.0f);

    // softmax
    softmax_rows<<<BSZ * NH * SEQ, 256>>>(sp);

    // attn @ V  (B = V natural [s, d] slice, NN)
    mma_gemm<64, 3><<<dim3(1, SEQ / 128, BSZ * NH), 256>>>(
        sp, vp, nullptr, nullptr, ap, SEQ, SEQ, EMB, EMB, 1.0f);

    // output projection
    mma_gemm<128, 0><<<gproj, 256>>>(ap, Wo, bo, nullptr, out,
                                     EMB, EMB, EMB, EMB, 1.0f);
}

// round 4
// speedup vs baseline: 2.3483x; 1.1992x over previous
#include <cuda_runtime.h>
#include <cstdint>
#include <math.h>

#define SEQ 1024
#define EMB 1024
#define BSZ 4
#define NH  16
#define HD  64
#define SCALING 0.125f
#define ATTN_CONST 3.032639477052158f

// ---------------- scratch (device globals; no allocations allowed) ----------
__device__ float g_q[BSZ * SEQ * EMB];
__device__ float g_k[BSZ * SEQ * EMB];
__device__ float g_v[BSZ * SEQ * EMB];
__device__ float g_attn[BSZ * SEQ * EMB];

__device__ __forceinline__ uint32_t f2tf(float x) {
    uint32_t r;
    asm("cvt.rna.tf32.f32 %0, %1;" : "=r"(r) : "f"(x));
    return r;
}
__device__ __forceinline__ uint4 cvt4(float4 v) {
    uint4 t;
    t.x = f2tf(v.x); t.y = f2tf(v.y); t.z = f2tf(v.z); t.w = f2tf(v.w);
    return t;
}
__device__ __forceinline__ void mma_tf32(float* c, const uint32_t* a, const uint32_t* b) {
    asm volatile(
        "mma.sync.aligned.m16n8k8.row.col.f32.tf32.tf32.f32 "
        "{%0,%1,%2,%3}, {%4,%5,%6,%7}, {%8,%9}, {%0,%1,%2,%3};"
        : "+f"(c[0]), "+f"(c[1]), "+f"(c[2]), "+f"(c[3])
        : "r"(a[0]), "r"(a[1]), "r"(a[2]), "r"(a[3]), "r"(b[0]), "r"(b[1]));
}

// ============ tf32 mma.sync GEMM (projections) ==============================
// C[m,n] = (sum_k A[m,k]*B[n,k] + bias[n]) * scale.  A MxK, B NxK row-major.
__global__ void __launch_bounds__(256, 1)
mma_gemm(const float* __restrict__ A, const float* __restrict__ B,
         const float* __restrict__ bias, float* __restrict__ C,
         int K, int lda, int ldb, int ldc, float scale)
{
    constexpr int BM = 128, BN = 128, BK = 16;
    constexpr int WROWS = 2, WM = 64, WN = 32, MI = 4, NI = 4;

    __shared__ uint32_t As[2][BM][BK + 4];
    __shared__ uint32_t Bs[2][BN][BK + 4];

    const int tid = threadIdx.x;
    const int wid = tid >> 5, lane = tid & 31;
    const int lq = lane >> 2, lr = lane & 3;
    const int warp_m = (wid % WROWS) * WM;
    const int warp_n = (wid / WROWS) * WN;
    const int m0 = blockIdx.y * BM;
    const int n0 = blockIdx.x * BN;

    float acc[MI][NI][4];
#pragma unroll
    for (int mi = 0; mi < MI; mi++)
#pragma unroll
        for (int ni = 0; ni < NI; ni++)
#pragma unroll
            for (int j = 0; j < 4; j++) acc[mi][ni][j] = 0.f;

    const int nk = K / BK;
    float4 pa[2], pb[2];
    auto ldg_tile = [&](int kk) {
        const float* Ag = A + (size_t)m0 * lda + kk * BK;
        const float* Bg = B + (size_t)n0 * ldb + kk * BK;
#pragma unroll
        for (int i = 0; i < 2; i++) {
            int e = tid + (i << 8);
            int r = e >> 2, c = (e & 3) << 2;
            pa[i] = *(const float4*)(Ag + (size_t)r * lda + c);
            pb[i] = *(const float4*)(Bg + (size_t)r * ldb + c);
        }
    };
    auto sts_tile = [&](int buf) {
#pragma unroll
        for (int i = 0; i < 2; i++) {
            int e = tid + (i << 8);
            int r = e >> 2, c = (e & 3) << 2;
            *(uint4*)&As[buf][r][c] = cvt4(pa[i]);
            *(uint4*)&Bs[buf][r][c] = cvt4(pb[i]);
        }
    };
    auto compute = [&](int buf) {
#pragma unroll
        for (int ks = 0; ks < 2; ks++) {
            const int k0 = ks * 8 + lr;
            uint32_t af[MI][4];
#pragma unroll
            for (int mi = 0; mi < MI; mi++) {
                int row = warp_m + mi * 16 + lq;
                af[mi][0] = As[buf][row][k0];
                af[mi][1] = As[buf][row + 8][k0];
                af[mi][2] = As[buf][row][k0 + 4];
                af[mi][3] = As[buf][row + 8][k0 + 4];
            }
            uint32_t bf[NI][2];
#pragma unroll
            for (int ni = 0; ni < NI; ni++) {
                int n = warp_n + ni * 8 + lq;
                bf[ni][0] = Bs[buf][n][k0];
                bf[ni][1] = Bs[buf][n][k0 + 4];
            }
#pragma unroll
            for (int mi = 0; mi < MI; mi++)
#pragma unroll
                for (int ni = 0; ni < NI; ni++)
                    mma_tf32(acc[mi][ni], af[mi], bf[ni]);
        }
    };

    ldg_tile(0);
    sts_tile(0);
    __syncthreads();
    for (int kk = 0; kk < nk; kk++) {
        if (kk + 1 < nk) ldg_tile(kk + 1);
        compute(kk & 1);
        if (kk + 1 < nk) sts_tile((kk + 1) & 1);
        __syncthreads();
    }

#pragma unroll
    for (int mi = 0; mi < MI; mi++) {
#pragma unroll
        for (int ni = 0; ni < NI; ni++) {
            int row = m0 + warp_m + mi * 16 + lq;
            int col = n0 + warp_n + ni * 8 + (lr << 1);
#pragma unroll
            for (int hh = 0; hh < 2; hh++) {
                int r = row + hh * 8;
                float2 bv = *(const float2*)(bias + col);
                float2 o = make_float2((acc[mi][ni][hh * 2 + 0] + bv.x) * scale,
                                       (acc[mi][ni][hh * 2 + 1] + bv.y) * scale);
                *(float2*)(C + (size_t)r * ldc + col) = o;
            }
        }
    }
}

// ================= fused flash attention ====================================
// grid (SEQ/128, BSZ*NH). Per CTA: 128 query rows of one head.
// O[b,m,h*64+d] = softmax_s( Q·K^T + ATTN_CONST*bias )·V
__global__ void __launch_bounds__(256, 1)
flash_attn(const float* __restrict__ Qg, const float* __restrict__ Kg,
           const float* __restrict__ Vg, const float* __restrict__ Bias,
           float* __restrict__ Og)
{
    extern __shared__ uint32_t sm[];
    uint32_t (*Qs)[68]     = (uint32_t(*)[68])sm;                          // 128x68
    uint32_t (*Ks)[64][68] = (uint32_t(*)[64][68])(sm + 128 * 68);         // 2x64x68
    uint32_t (*Vs)[64][68] = (uint32_t(*)[64][68])(sm + 128 * 68 + 2 * 64 * 68);
    uint32_t (*Ps)[68]     = (uint32_t(*)[68])(sm + 128 * 68 + 4 * 64 * 68);

    const int tid = threadIdx.x;
    const int wid = tid >> 5, lane = tid & 31;
    const int lq = lane >> 2, lr = lane & 3;
    const int wrow = wid * 16;
    const int m0 = blockIdx.x * 128;
    const int bh = blockIdx.y;
    const int b = bh >> 4, h = bh & 15;

    const float* Qp = Qg + ((size_t)b * SEQ + m0) * EMB + h * HD;
    const float* Kp = Kg + (size_t)b * SEQ * EMB + h * HD;
    const float* Vp = Vg + (size_t)b * SEQ * EMB + h * HD;

    // load Q tile (128 x 64)
#pragma unroll
    for (int i = 0; i < 8; i++) {
        int e = tid + (i << 8);
        int r = e >> 4, c = (e & 15) << 2;
        float4 v = *(const float4*)(Qp + (size_t)r * EMB + c);
        *(uint4*)&Qs[r][c] = cvt4(v);
    }

    float4 kreg[4], vreg[4];
    auto ldgKV = [&](int kb) {
#pragma unroll
        for (int i = 0; i < 4; i++) {
            int e = tid + (i << 8);
            int r = e >> 4, c = (e & 15) << 2;
            kreg[i] = *(const float4*)(Kp + (size_t)(kb * 64 + r) * EMB + c);
            vreg[i] = *(const float4*)(Vp + (size_t)(kb * 64 + r) * EMB + c);
        }
    };
    auto stsKV = [&](int buf) {
#pragma unroll
        for (int i = 0; i < 4; i++) {
            int e = tid + (i << 8);
            int r = e >> 4, c = (e & 15) << 2;
            *(uint4*)&Ks[buf][r][c] = cvt4(kreg[i]);
            *(uint4*)&Vs[buf][r][c] = cvt4(vreg[i]);
        }
    };

    float oacc[8][4];
#pragma unroll
    for (int ni = 0; ni < 8; ni++)
#pragma unroll
        for (int j = 0; j < 4; j++) oacc[ni][j] = 0.f;
    float mrun0 = -1e30f, mrun1 = -1e30f, lrun0 = 0.f, lrun1 = 0.f;

    ldgKV(0);
    stsKV(0);
    __syncthreads();

    for (int kb = 0; kb < 16; kb++) {
        const int buf = kb & 1;
        if (kb + 1 < 16) ldgKV(kb + 1);

        // ---- S = Q @ K^T (128x64, K=64) ----
        float sacc[8][4];
#pragma unroll
        for (int ni = 0; ni < 8; ni++)
#pragma unroll
            for (int j = 0; j < 4; j++) sacc[ni][j] = 0.f;
#pragma unroll
        for (int ks = 0; ks < 8; ks++) {
            const int k0 = ks * 8 + lr;
            uint32_t af[4];
            af[0] = Qs[wrow + lq][k0];
            af[1] = Qs[wrow + lq + 8][k0];
            af[2] = Qs[wrow + lq][k0 + 4];
            af[3] = Qs[wrow + lq + 8][k0 + 4];
#pragma unroll
            for (int ni = 0; ni < 8; ni++) {
                uint32_t bf[2];
                bf[0] = Ks[buf][ni * 8 + lq][k0];
                bf[1] = Ks[buf][ni * 8 + lq][k0 + 4];
                mma_tf32(sacc[ni], af, bf);
            }
        }

        // ---- bias add (streamed from gmem) ----
        {
            const float* bp0 = Bias + ((size_t)bh * SEQ + (m0 + wrow + lq)) * SEQ + kb * 64;
            const float* bp1 = bp0 + (size_t)8 * SEQ;
#pragma unroll
            for (int ni = 0; ni < 8; ni++) {
                int c = ni * 8 + (lr << 1);
                float2 b0 = *(const float2*)(bp0 + c);
                float2 b1 = *(const float2*)(bp1 + c);
                sacc[ni][0] += ATTN_CONST * b0.x;
                sacc[ni][1] += ATTN_CONST * b0.y;
                sacc[ni][2] += ATTN_CONST * b1.x;
                sacc[ni][3] += ATTN_CONST * b1.y;
            }
        }

        // ---- online softmax (rows lq, lq+8 of warp tile) ----
        float mx0 = -1e30f, mx1 = -1e30f;
#pragma unroll
        for (int ni = 0; ni < 8; ni++) {
            mx0 = fmaxf(mx0, fmaxf(sacc[ni][0], sacc[ni][1]));
            mx1 = fmaxf(mx1, fmaxf(sacc[ni][2], sacc[ni][3]));
        }
        mx0 = fmaxf(mx0, __shfl_xor_sync(0xffffffffu, mx0, 1));
        mx0 = fmaxf(mx0, __shfl_xor_sync(0xffffffffu, mx0, 2));
        mx1 = fmaxf(mx1, __shfl_xor_sync(0xffffffffu, mx1, 1));
        mx1 = fmaxf(mx1, __shfl_xor_sync(0xffffffffu, mx1, 2));
        const float mn0 = fmaxf(mrun0, mx0), mn1 = fmaxf(mrun1, mx1);
        const float sc0 = __expf(mrun0 - mn0), sc1 = __expf(mrun1 - mn1);
        float sum0 = 0.f, sum1 = 0.f;
#pragma unroll
        for (int ni = 0; ni < 8; ni++) {
            sacc[ni][0] = __expf(sacc[ni][0] - mn0);
            sacc[ni][1] = __expf(sacc[ni][1] - mn0);
            sacc[ni][2] = __expf(sacc[ni][2] - mn1);
            sacc[ni][3] = __expf(sacc[ni][3] - mn1);
            sum0 += sacc[ni][0] + sacc[ni][1];
            sum1 += sacc[ni][2] + sacc[ni][3];
        }
        sum0 += __shfl_xor_sync(0xffffffffu, sum0, 1);
        sum0 += __shfl_xor_sync(0xffffffffu, sum0, 2);
        sum1 += __shfl_xor_sync(0xffffffffu, sum1, 1);
        sum1 += __shfl_xor_sync(0xffffffffu, sum1, 2);
        lrun0 = lrun0 * sc0 + sum0;
        lrun1 = lrun1 * sc1 + sum1;
        mrun0 = mn0; mrun1 = mn1;
#pragma unroll
        for (int ni = 0; ni < 8; ni++) {
            oacc[ni][0] *= sc0; oacc[ni][1] *= sc0;
            oacc[ni][2] *= sc1; oacc[ni][3] *= sc1;
        }

        if (kb + 1 < 16) stsKV(buf ^ 1);

        // ---- P -> smem (tf32) ----
#pragma unroll
        for (int ni = 0; ni < 8; ni++) {
            int c = ni * 8 + (lr << 1);
            Ps[wrow + lq][c]         = f2tf(sacc[ni][0]);
            Ps[wrow + lq][c + 1]     = f2tf(sacc[ni][1]);
            Ps[wrow + lq + 8][c]     = f2tf(sacc[ni][2]);
            Ps[wrow + lq + 8][c + 1] = f2tf(sacc[ni][3]);
        }
        __syncthreads();

        // ---- O += P @ V (128x64, K=64) ----
#pragma unroll
        for (int ks = 0; ks < 8; ks++) {
            const int k0 = ks * 8 + lr;
            uint32_t af[4];
            af[0] = Ps[wrow + lq][k0];
            af[1] = Ps[wrow + lq + 8][k0];
            af[2] = Ps[wrow + lq][k0 + 4];
            af[3] = Ps[wrow + lq + 8][k0 + 4];
#pragma unroll
            for (int ni = 0; ni < 8; ni++) {
                uint32_t bf[2];
                bf[0] = Vs[buf][k0][ni * 8 + lq];
                bf[1] = Vs[buf][k0 + 4][ni * 8 + lq];
                mma_tf32(oacc[ni], af, bf);
            }
        }
        __syncthreads();
    }

    // ---- epilogue: normalize + store ----
    const float inv0 = 1.0f / lrun0, inv1 = 1.0f / lrun1;
    float* Op0 = Og + ((size_t)b * SEQ + (m0 + wrow + lq)) * EMB + h * HD;
    float* Op1 = Op0 + (size_t)8 * EMB;
#pragma unroll
    for (int ni = 0; ni < 8; ni++) {
        int c = ni * 8 + (lr << 1);
        *(float2*)(Op0 + c) = make_float2(oacc[ni][0] * inv0, oacc[ni][1] * inv0);
        *(float2*)(Op1 + c) = make_float2(oacc[ni][2] * inv1, oacc[ni][3] * inv1);
    }
}

// ---------------- launcher ---------------------------------------------------
extern "C" void kernel_launch(void* const* d_in, const int* in_sizes, int n_in,
                              void* d_out, int out_size)
{
    const float* hidden = (const float*)d_in[0];
    const float* attn_b = (const float*)d_in[1];
    const float* Wq = (const float*)d_in[2];
    const float* bq = (const float*)d_in[3];
    const float* Wk = (const float*)d_in[4];
    const float* bk = (const float*)d_in[5];
    const float* Wv = (const float*)d_in[6];
    const float* bv = (const float*)d_in[7];
    const float* Wo = (const float*)d_in[8];
    const float* bo = (const float*)d_in[9];
    float* out = (float*)d_out;

    float *qp, *kp, *vp, *ap;
    cudaGetSymbolAddress((void**)&qp, g_q);
    cudaGetSymbolAddress((void**)&kp, g_k);
    cudaGetSymbolAddress((void**)&vp, g_v);
    cudaGetSymbolAddress((void**)&ap, g_attn);

    const int FLASH_SMEM = (128 * 68 + 4 * 64 * 68 + 128 * 68) * 4;  // 139264
    cudaFuncSetAttribute(flash_attn, cudaFuncAttributeMaxDynamicSharedMemorySize, FLASH_SMEM);

    dim3 gproj(EMB / 128, (BSZ * SEQ) / 128, 1);   // (8, 32)

    // QKV projections (q pre-scaled by SCALING)
    mma_gemm<<<gproj, 256>>>(hidden, Wq, bq, qp, EMB, EMB, EMB, EMB, SCALING);
    mma_gemm<<<gproj, 256>>>(hidden, Wk, bk, kp, EMB, EMB, EMB, EMB, 1.0f);
    mma_gemm<<<gproj, 256>>>(hidden, Wv, bv, vp, EMB, EMB, EMB, EMB, 1.0f);

    // fused attention
    flash_attn<<<dim3(SEQ / 128, BSZ * NH), 256, FLASH_SMEM>>>(qp, kp, vp, attn_b, ap);

    // output projection
    mma_gemm<<<gproj, 256>>>(ap, Wo, bo, out, EMB, EMB, EMB, EMB, 1.0f);
}

// round 5
// speedup vs baseline: 3.7583x; 1.6004x over previous
#include <cuda_runtime.h>
#include <cuda_fp16.h>
#include <cstdint>
#include <math.h>

#define SEQ 1024
#define EMB 1024
#define BSZ 4
#define NH  16
#define HD  64
#define SCALING 0.125f
#define ATTN_CONST 3.032639477052158f

// ---------------- scratch (device globals; no allocations allowed) ----------
__device__ float g_q[BSZ * SEQ * EMB];
__device__ float g_k[BSZ * SEQ * EMB];
__device__ float g_v[BSZ * SEQ * EMB];
__device__ float g_attn[BSZ * SEQ * EMB];

__device__ __forceinline__ uint32_t h2u(__half2 h) { return *(uint32_t*)&h; }
__device__ __forceinline__ uint2 pack4h(float4 v) {
    __half2 a = __floats2half2_rn(v.x, v.y);
    __half2 b = __floats2half2_rn(v.z, v.w);
    return make_uint2(h2u(a), h2u(b));
}
// fp16 mma, fp32 accumulate: D(16x8) += A(16x16) * B(16x8)
__device__ __forceinline__ void mma_f16(float* c, const uint32_t* a, const uint32_t* b) {
    asm volatile(
        "mma.sync.aligned.m16n8k16.row.col.f32.f16.f16.f32 "
        "{%0,%1,%2,%3}, {%4,%5,%6,%7}, {%8,%9}, {%0,%1,%2,%3};"
        : "+f"(c[0]), "+f"(c[1]), "+f"(c[2]), "+f"(c[3])
        : "r"(a[0]), "r"(a[1]), "r"(a[2]), "r"(a[3]), "r"(b[0]), "r"(b[1]));
}

// ============ fp16 mma.sync GEMM (projections) ==============================
// C[m,n] = (sum_k A[m,k]*W[n,k] + b[n]) * (z==0 ? scale0 : 1)
// grid.z selects (W,b,C) triple; BM=BN=128, BK=32, 256 threads.
__global__ void __launch_bounds__(256, 1)
mma_gemm3(const float* __restrict__ A,
          const float* __restrict__ W0, const float* __restrict__ W1,
          const float* __restrict__ W2,
          const float* __restrict__ b0, const float* __restrict__ b1,
          const float* __restrict__ b2,
          float* __restrict__ C0, float* __restrict__ C1, float* __restrict__ C2,
          float scale0)
{
    constexpr int BM = 128, BN = 128, BK = 32;
    constexpr int WROWS = 2, WM = 64, WN = 32, MI = 4, NI = 4;

    __shared__ __half As[2][BM][BK + 8];   // stride 40 halves = 20 words
    __shared__ __half Bs[2][BN][BK + 8];

    const int z = blockIdx.z;
    const float* B = (z == 0) ? W0 : (z == 1) ? W1 : W2;
    const float* bias = (z == 0) ? b0 : (z == 1) ? b1 : b2;
    float* C = (z == 0) ? C0 : (z == 1) ? C1 : C2;
    const float scale = (z == 0) ? scale0 : 1.0f;

    const int tid = threadIdx.x;
    const int wid = tid >> 5, lane = tid & 31;
    const int lq = lane >> 2, lr = lane & 3;
    const int warp_m = (wid % WROWS) * WM;
    const int warp_n = (wid / WROWS) * WN;
    const int m0 = blockIdx.y * BM;
    const int n0 = blockIdx.x * BN;

    float acc[MI][NI][4];
#pragma unroll
    for (int mi = 0; mi < MI; mi++)
#pragma unroll
        for (int ni = 0; ni < NI; ni++)
#pragma unroll
            for (int j = 0; j < 4; j++) acc[mi][ni][j] = 0.f;

    const int nk = EMB / BK;   // 32
    float4 pa[4], pb[4];
    auto ldg_tile = [&](int kk) {
        const float* Ag = A + (size_t)m0 * EMB + kk * BK;
        const float* Bg = B + (size_t)n0 * EMB + kk * BK;
#pragma unroll
        for (int i = 0; i < 4; i++) {
            int e = tid + (i << 8);
            int r = e >> 3, c = (e & 7) << 2;
            pa[i] = *(const float4*)(Ag + (size_t)r * EMB + c);
            pb[i] = *(const float4*)(Bg + (size_t)r * EMB + c);
        }
    };
    auto sts_tile = [&](int buf) {
#pragma unroll
        for (int i = 0; i < 4; i++) {
            int e = tid + (i << 8);
            int r = e >> 3, c = (e & 7) << 2;
            *(uint2*)&As[buf][r][c] = pack4h(pa[i]);
            *(uint2*)&Bs[buf][r][c] = pack4h(pb[i]);
        }
    };
    auto compute = [&](int buf) {
#pragma unroll
        for (int ks = 0; ks < 2; ks++) {
            uint32_t af[MI][4];
#pragma unroll
            for (int mi = 0; mi < MI; mi++) {
                const uint32_t* r0 = (const uint32_t*)As[buf][warp_m + mi * 16 + lq];
                const uint32_t* r1 = (const uint32_t*)As[buf][warp_m + mi * 16 + lq + 8];
                af[mi][0] = r0[8 * ks + lr];
                af[mi][1] = r1[8 * ks + lr];
                af[mi][2] = r0[8 * ks + lr + 4];
                af[mi][3] = r1[8 * ks + lr + 4];
            }
            uint32_t bf[NI][2];
#pragma unroll
            for (int ni = 0; ni < NI; ni++) {
                const uint32_t* rn = (const uint32_t*)Bs[buf][warp_n + ni * 8 + lq];
                bf[ni][0] = rn[8 * ks + lr];
                bf[ni][1] = rn[8 * ks + lr + 4];
            }
#pragma unroll
            for (int mi = 0; mi < MI; mi++)
#pragma unroll
                for (int ni = 0; ni < NI; ni++)
                    mma_f16(acc[mi][ni], af[mi], bf[ni]);
        }
    };

    ldg_tile(0);
    sts_tile(0);
    __syncthreads();
    for (int kk = 0; kk < nk; kk++) {
        if (kk + 1 < nk) ldg_tile(kk + 1);
        compute(kk & 1);
        if (kk + 1 < nk) sts_tile((kk + 1) & 1);
        __syncthreads();
    }

#pragma unroll
    for (int mi = 0; mi < MI; mi++) {
#pragma unroll
        for (int ni = 0; ni < NI; ni++) {
            int row = m0 + warp_m + mi * 16 + lq;
            int col = n0 + warp_n + ni * 8 + (lr << 1);
            float2 bv = *(const float2*)(bias + col);
#pragma unroll
            for (int hh = 0; hh < 2; hh++) {
                int r = row + hh * 8;
                float2 o = make_float2((acc[mi][ni][hh * 2 + 0] + bv.x) * scale,
                                       (acc[mi][ni][hh * 2 + 1] + bv.y) * scale);
                *(float2*)(C + (size_t)r * EMB + col) = o;
            }
        }
    }
}

// ================= fused flash attention (fp16 mma) =========================
// grid (SEQ/128, BSZ*NH). 256 threads / 8 warps, 16 rows per warp.
// P stays in registers: m16n8k16 C-fragment == A-fragment layout.
__global__ void __launch_bounds__(256, 1)
flash_attn(const float* __restrict__ Qg, const float* __restrict__ Kg,
           const float* __restrict__ Vg, const float* __restrict__ Bias,
           float* __restrict__ Og)
{
    extern __shared__ __align__(16) __half sm[];
    __half (*Qs)[72]     = (__half(*)[72])sm;                        // 128x72
    __half (*Ks)[64][72] = (__half(*)[64][72])(sm + 128 * 72);       // 2x64x72
    __half (*Vt)[64][72] = (__half(*)[64][72])(sm + 128 * 72 + 2 * 64 * 72); // [d][s]

    const int tid = threadIdx.x;
    const int wid = tid >> 5, lane = tid & 31;
    const int lq = lane >> 2, lr = lane & 3;
    const int wrow = wid * 16;
    const int m0 = blockIdx.x * 128;
    const int bh = blockIdx.y;
    const int b = bh >> 4, h = bh & 15;

    const float* Qp = Qg + ((size_t)b * SEQ + m0) * EMB + h * HD;
    const float* Kp = Kg + (size_t)b * SEQ * EMB + h * HD;
    const float* Vp = Vg + (size_t)b * SEQ * EMB + h * HD;

    // Q tile (128 x 64) -> fp16 smem
#pragma unroll
    for (int i = 0; i < 8; i++) {
        int e = tid + (i << 8);
        int r = e >> 4, c = (e & 15) << 2;
        *(uint2*)&Qs[r][c] = pack4h(*(const float4*)(Qp + (size_t)r * EMB + c));
    }

    float4 kreg[4], vreg[4];
    auto ldgKV = [&](int kb) {
#pragma unroll
        for (int i = 0; i < 4; i++) {
            int e = tid + (i << 8);
            int r = e >> 4, c = (e & 15) << 2;
            kreg[i] = *(const float4*)(Kp + (size_t)(kb * 64 + r) * EMB + c);
            vreg[i] = *(const float4*)(Vp + (size_t)(kb * 64 + r) * EMB + c);
        }
    };
    auto stsKV = [&](int buf) {
#pragma unroll
        for (int i = 0; i < 4; i++) {
            int e = tid + (i << 8);
            int r = e >> 4, c = (e & 15) << 2;        // r = s-row, c = d-col
            *(uint2*)&Ks[buf][r][c] = pack4h(kreg[i]);
            Vt[buf][c + 0][r] = __float2half_rn(vreg[i].x);   // transpose to [d][s]
            Vt[buf][c + 1][r] = __float2half_rn(vreg[i].y);
            Vt[buf][c + 2][r] = __float2half_rn(vreg[i].z);
            Vt[buf][c + 3][r] = __float2half_rn(vreg[i].w);
        }
    };

    float oacc[8][4];
#pragma unroll
    for (int ni = 0; ni < 8; ni++)
#pragma unroll
        for (int j = 0; j < 4; j++) oacc[ni][j] = 0.f;
    float mrun0 = -1e30f, mrun1 = -1e30f, lrun0 = 0.f, lrun1 = 0.f;

    const uint32_t* qr0 = (const uint32_t*)Qs[wrow + lq];
    const uint32_t* qr1 = (const uint32_t*)Qs[wrow + lq + 8];

    ldgKV(0);
    stsKV(0);
    __syncthreads();

    for (int kb = 0; kb < 16; kb++) {
        const int buf = kb & 1;
        if (kb + 1 < 16) ldgKV(kb + 1);

        // bias prefetch (latency hidden under QK mma)
        float2 br0[8], br1[8];
        {
            const float* bp0 = Bias + ((size_t)bh * SEQ + (m0 + wrow + lq)) * SEQ + kb * 64;
            const float* bp1 = bp0 + (size_t)8 * SEQ;
#pragma unroll
            for (int ni = 0; ni < 8; ni++) {
                int c = ni * 8 + (lr << 1);
                br0[ni] = *(const float2*)(bp0 + c);
                br1[ni] = *(const float2*)(bp1 + c);
            }
        }

        // ---- S = Q @ K^T (128x64, k=64 over d) ----
        float sacc[8][4];
#pragma unroll
        for (int ni = 0; ni < 8; ni++)
#pragma unroll
            for (int j = 0; j < 4; j++) sacc[ni][j] = 0.f;
#pragma unroll
        for (int ks = 0; ks < 4; ks++) {
            uint32_t a[4];
            a[0] = qr0[8 * ks + lr];
            a[1] = qr1[8 * ks + lr];
            a[2] = qr0[8 * ks + lr + 4];
            a[3] = qr1[8 * ks + lr + 4];
#pragma unroll
            for (int ni = 0; ni < 8; ni++) {
                const uint32_t* kr = (const uint32_t*)Ks[buf][ni * 8 + lq];
                uint32_t bfr[2] = {kr[8 * ks + lr], kr[8 * ks + lr + 4]};
                mma_f16(sacc[ni], a, bfr);
            }
        }

        // ---- bias add ----
#pragma unroll
        for (int ni = 0; ni < 8; ni++) {
            sacc[ni][0] += ATTN_CONST * br0[ni].x;
            sacc[ni][1] += ATTN_CONST * br0[ni].y;
            sacc[ni][2] += ATTN_CONST * br1[ni].x;
            sacc[ni][3] += ATTN_CONST * br1[ni].y;
        }

        // ---- online softmax (rows lq, lq+8 of this warp) ----
        float mx0 = -1e30f, mx1 = -1e30f;
#pragma unroll
        for (int ni = 0; ni < 8; ni++) {
            mx0 = fmaxf(mx0, fmaxf(sacc[ni][0], sacc[ni][1]));
            mx1 = fmaxf(mx1, fmaxf(sacc[ni][2], sacc[ni][3]));
        }
        mx0 = fmaxf(mx0, __shfl_xor_sync(0xffffffffu, mx0, 1));
        mx0 = fmaxf(mx0, __shfl_xor_sync(0xffffffffu, mx0, 2));
        mx1 = fmaxf(mx1, __shfl_xor_sync(0xffffffffu, mx1, 1));
        mx1 = fmaxf(mx1, __shfl_xor_sync(0xffffffffu, mx1, 2));
        const float mn0 = fmaxf(mrun0, mx0), mn1 = fmaxf(mrun1, mx1);
        const float sc0 = __expf(mrun0 - mn0), sc1 = __expf(mrun1 - mn1);
        float sum0 = 0.f, sum1 = 0.f;
#pragma unroll
        for (int ni = 0; ni < 8; ni++) {
            sacc[ni][0] = __expf(sacc[ni][0] - mn0);
            sacc[ni][1] = __expf(sacc[ni][1] - mn0);
            sacc[ni][2] = __expf(sacc[ni][2] - mn1);
            sacc[ni][3] = __expf(sacc[ni][3] - mn1);
            sum0 += sacc[ni][0] + sacc[ni][1];
            sum1 += sacc[ni][2] + sacc[ni][3];
        }
        sum0 += __shfl_xor_sync(0xffffffffu, sum0, 1);
        sum0 += __shfl_xor_sync(0xffffffffu, sum0, 2);
        sum1 += __shfl_xor_sync(0xffffffffu, sum1, 1);
        sum1 += __shfl_xor_sync(0xffffffffu, sum1, 2);
        lrun0 = lrun0 * sc0 + sum0;
        lrun1 = lrun1 * sc1 + sum1;
        mrun0 = mn0; mrun1 = mn1;
#pragma unroll
        for (int ni = 0; ni < 8; ni++) {
            oacc[ni][0] *= sc0; oacc[ni][1] *= sc0;
            oacc[ni][2] *= sc1; oacc[ni][3] *= sc1;
        }

        // ---- P -> fp16 registers (C-frag == A-frag layout, zero shuffle) ----
        uint32_t pl[8], pu[8];
#pragma unroll
        for (int ni = 0; ni < 8; ni++) {
            pl[ni] = h2u(__floats2half2_rn(sacc[ni][0], sacc[ni][1]));
            pu[ni] = h2u(__floats2half2_rn(sacc[ni][2], sacc[ni][3]));
        }

        if (kb + 1 < 16) stsKV(buf ^ 1);

        // ---- O += P @ V (k=64 over s) ----
#pragma unroll
        for (int ks = 0; ks < 4; ks++) {
            uint32_t a[4] = {pl[2 * ks], pu[2 * ks], pl[2 * ks + 1], pu[2 * ks + 1]};
#pragma unroll
            for (int ni = 0; ni < 8; ni++) {
                const uint32_t* vr = (const uint32_t*)Vt[buf][ni * 8 + lq];
                uint32_t bfr[2] = {vr[8 * ks + lr], vr[8 * ks + lr + 4]};
                mma_f16(oacc[ni], a, bfr);
            }
        }
        __syncthreads();   // KV double-buffer handoff (only sync in loop)
    }

    // ---- epilogue: normalize + store ----
    const float inv0 = 1.0f / lrun0, inv1 = 1.0f / lrun1;
    float* Op0 = Og + ((size_t)b * SEQ + (m0 + wrow + lq)) * EMB + h * HD;
    float* Op1 = Op0 + (size_t)8 * EMB;
#pragma unroll
    for (int ni = 0; ni < 8; ni++) {
        int c = ni * 8 + (lr << 1);
        *(float2*)(Op0 + c) = make_float2(oacc[ni][0] * inv0, oacc[ni][1] * inv0);
        *(float2*)(Op1 + c) = make_float2(oacc[ni][2] * inv1, oacc[ni][3] * inv1);
    }
}

// ---------------- launcher ---------------------------------------------------
extern "C" void kernel_launch(void* const* d_in, const int* in_sizes, int n_in,
                              void* d_out, int out_size)
{
    const float* hidden = (const float*)d_in[0];
    const float* attn_b = (const float*)d_in[1];
    const float* Wq = (const float*)d_in[2];
    const float* bq = (const float*)d_in[3];
    const float* Wk = (const float*)d_in[4];
    const float* bk = (const float*)d_in[5];
    const float* Wv = (const float*)d_in[6];
    const float* bv = (const float*)d_in[7];
    const float* Wo = (const float*)d_in[8];
    const float* bo = (const float*)d_in[9];
    float* out = (float*)d_out;

    float *qp, *kp, *vp, *ap;
    cudaGetSymbolAddress((void**)&qp, g_q);
    cudaGetSymbolAddress((void**)&kp, g_k);
    cudaGetSymbolAddress((void**)&vp, g_v);
    cudaGetSymbolAddress((void**)&ap, g_attn);

    const int FLASH_SMEM = (128 * 72 + 2 * 64 * 72 + 2 * 64 * 72) * 2;  // 55296
    cudaFuncSetAttribute(flash_attn, cudaFuncAttributeMaxDynamicSharedMemorySize, FLASH_SMEM);

    // fused QKV projections (z selects W/b/C; q pre-scaled by SCALING)
    mma_gemm3<<<dim3(EMB / 128, (BSZ * SEQ) / 128, 3), 256>>>(
        hidden, Wq, Wk, Wv, bq, bk, bv, qp, kp, vp, SCALING);

    // fused attention
    flash_attn<<<dim3(SEQ / 128, BSZ * NH), 256, FLASH_SMEM>>>(qp, kp, vp, attn_b, ap);

    // output projection
    mma_gemm3<<<dim3(EMB / 128, (BSZ * SEQ) / 128, 1), 256>>>(
        ap, Wo, Wo, Wo, bo, bo, bo, out, out, out, 1.0f);
}

// round 6
// speedup vs baseline: 5.4873x; 1.4600x over previous
#include <cuda_runtime.h>
#include <cuda_fp16.h>
#include <cstdint>
#include <math.h>

#define SEQ 1024
#define EMB 1024
#define BSZ 4
#define NH  16
#define HD  64
#define SCALING 0.125f
#define ATTN_CONST 3.032639477052158f

// ---------------- fp16 scratch (device globals) -----------------------------
__device__ __half g_h16[BSZ * SEQ * EMB];
__device__ __half g_w16[4][EMB * EMB];
__device__ __half g_q16[BSZ * SEQ * EMB];
__device__ __half g_k16[BSZ * SEQ * EMB];
__device__ __half g_v16[BSZ * SEQ * EMB];
__device__ __half g_a16[BSZ * SEQ * EMB];

// ---------------- helpers ----------------------------------------------------
__device__ __forceinline__ uint32_t h2u(__half2 h) { return *(uint32_t*)&h; }
__device__ __forceinline__ uint32_t smem_u32(const void* p) {
    uint32_t a;
    asm("{ .reg .u64 t; cvta.to.shared.u64 t, %1; cvt.u32.u64 %0, t; }" : "=r"(a) : "l"(p));
    return a;
}
__device__ __forceinline__ void cp16(uint32_t dst, const void* src) {
    asm volatile("cp.async.ca.shared.global [%0], [%1], 16;" :: "r"(dst), "l"(src));
}
__device__ __forceinline__ void cp_commit() { asm volatile("cp.async.commit_group;" ::: "memory"); }
template <int N>
__device__ __forceinline__ void cp_wait() {
    asm volatile("cp.async.wait_group %0;" :: "n"(N) : "memory");
}
__device__ __forceinline__ void ldsm4(uint32_t* r, uint32_t addr) {
    asm volatile("ldmatrix.sync.aligned.m8n8.x4.shared.b16 {%0,%1,%2,%3}, [%4];"
                 : "=r"(r[0]), "=r"(r[1]), "=r"(r[2]), "=r"(r[3]) : "r"(addr));
}
__device__ __forceinline__ void ldsm4t(uint32_t* r, uint32_t addr) {
    asm volatile("ldmatrix.sync.aligned.m8n8.x4.trans.shared.b16 {%0,%1,%2,%3}, [%4];"
                 : "=r"(r[0]), "=r"(r[1]), "=r"(r[2]), "=r"(r[3]) : "r"(addr));
}
// Swizzle<3,3,3>: rows of 64 halves (128B), 8 chunks of 16B; byte offset in tile
__device__ __forceinline__ uint32_t swz(int r, int chunk) {
    return (uint32_t)(r * 128 + ((chunk ^ (r & 7)) << 4));
}
__device__ __forceinline__ void mma_f16(float* c, const uint32_t* a, const uint32_t* b) {
    asm volatile(
        "mma.sync.aligned.m16n8k16.row.col.f32.f16.f16.f32 "
        "{%0,%1,%2,%3}, {%4,%5,%6,%7}, {%8,%9}, {%0,%1,%2,%3};"
        : "+f"(c[0]), "+f"(c[1]), "+f"(c[2]), "+f"(c[3])
        : "r"(a[0]), "r"(a[1]), "r"(a[2]), "r"(a[3]), "r"(b[0]), "r"(b[1]));
}

// ---------------- f32 -> fp16 convert ---------------------------------------
__global__ void __launch_bounds__(256)
f32to16(const float4* __restrict__ src, uint2* __restrict__ dst, int n4)
{
    int i = blockIdx.x * blockDim.x + threadIdx.x;
    if (i < n4) {
        float4 v = src[i];
        dst[i] = make_uint2(h2u(__floats2half2_rn(v.x, v.y)),
                            h2u(__floats2half2_rn(v.z, v.w)));
    }
}

// ============ fp16 GEMM: C = (A @ W^T + b) * scale ==========================
// A: MxK fp16 row-major. W: NxK fp16 row-major. 512 threads, BM=BN=128, BK=64.
// 3-stage cp.async + ldmatrix. OUT16 -> fp16 C, else f32 C.
template <bool OUT16>
__global__ void __launch_bounds__(512, 1)
hgemm(const __half* __restrict__ A,
      const __half* __restrict__ W0, const __half* __restrict__ W1,
      const __half* __restrict__ W2,
      const float* __restrict__ b0, const float* __restrict__ b1,
      const float* __restrict__ b2,
      void* __restrict__ C0, void* __restrict__ C1, void* __restrict__ C2,
      float scale0)
{
    extern __shared__ __align__(16) char smem[];
    const uint32_t sb = smem_u32(smem);
    // A stage s: sb + s*16384 ; W stage s: sb + 49152 + s*16384

    const int z = blockIdx.z;
    const __half* W = (z == 0) ? W0 : (z == 1) ? W1 : W2;
    const float* bias = (z == 0) ? b0 : (z == 1) ? b1 : b2;
    void* C = (z == 0) ? C0 : (z == 1) ? C1 : C2;
    const float scale = (z == 0) ? scale0 : 1.0f;

    const int tid = threadIdx.x;
    const int wid = tid >> 5, lane = tid & 31;
    const int lq = lane >> 2, lr = lane & 3;
    const int lrow = lane & 15, lhi = lane >> 4, l8 = lane & 7, lg = (lane >> 3) & 1;
    const int warp_m = (wid & 3) * 32, warp_n = (wid >> 2) * 32;
    const int m0 = blockIdx.y * 128, n0 = blockIdx.x * 128;

    float acc[2][4][4];
#pragma unroll
    for (int mi = 0; mi < 2; mi++)
#pragma unroll
        for (int ni = 0; ni < 4; ni++)
#pragma unroll
            for (int j = 0; j < 4; j++) acc[mi][ni][j] = 0.f;

    auto issue = [&](int kk, int s) {
        const __half* Ag = A + (size_t)m0 * EMB + kk * 64;
        const __half* Wg = W + (size_t)n0 * EMB + kk * 64;
        uint32_t ab = sb + s * 16384u, bb = sb + 49152u + s * 16384u;
#pragma unroll
        for (int i = 0; i < 2; i++) {
            int q = tid + (i << 9);
            int r = q >> 3, c = q & 7;
            cp16(ab + swz(r, c), Ag + (size_t)r * EMB + c * 8);
            cp16(bb + swz(r, c), Wg + (size_t)r * EMB + c * 8);
        }
    };
    issue(0, 0); cp_commit();
    issue(1, 1); cp_commit();

    for (int kk = 0; kk < 16; kk++) {
        cp_wait<1>();
        __syncthreads();
        if (kk + 2 < 16) issue(kk + 2, (kk + 2) % 3);
        cp_commit();

        const int s = kk % 3;
        const uint32_t ab = sb + s * 16384u, bb = sb + 49152u + s * 16384u;
#pragma unroll
        for (int ks = 0; ks < 4; ks++) {
            uint32_t af[2][4], bf[2][4];
#pragma unroll
            for (int mi = 0; mi < 2; mi++)
                ldsm4(af[mi], ab + swz(warp_m + mi * 16 + lrow, ks * 2 + lhi));
#pragma unroll
            for (int np = 0; np < 2; np++)
                ldsm4(bf[np], bb + swz(warp_n + (np * 2 + lhi) * 8 + l8, ks * 2 + lg));
#pragma unroll
            for (int mi = 0; mi < 2; mi++)
#pragma unroll
                for (int ni = 0; ni < 4; ni++)
                    mma_f16(acc[mi][ni], af[mi], &bf[ni >> 1][(ni & 1) * 2]);
        }
    }

#pragma unroll
    for (int mi = 0; mi < 2; mi++) {
#pragma unroll
        for (int ni = 0; ni < 4; ni++) {
            int row = m0 + warp_m + mi * 16 + lq;
            int col = n0 + warp_n + ni * 8 + (lr << 1);
            float2 bv = *(const float2*)(bias + col);
#pragma unroll
            for (int hh = 0; hh < 2; hh++) {
                int r = row + hh * 8;
                float x = (acc[mi][ni][hh * 2 + 0] + bv.x) * scale;
                float y = (acc[mi][ni][hh * 2 + 1] + bv.y) * scale;
                if (OUT16)
                    *(__half2*)((__half*)C + (size_t)r * EMB + col) = __floats2half2_rn(x, y);
                else
                    *(float2*)((float*)C + (size_t)r * EMB + col) = make_float2(x, y);
            }
        }
    }
}

// ================= fused flash attention (fp16 in/out) ======================
// grid (SEQ/128, BSZ*NH), 256 threads. cp.async 3-stage KV, ldmatrix frags,
// P in registers, V consumed via ldmatrix.trans (no transpose on store).
__global__ void __launch_bounds__(256, 1)
flash16(const __half* __restrict__ Qg, const __half* __restrict__ Kg,
        const __half* __restrict__ Vg, const float* __restrict__ Bias,
        __half* __restrict__ Og)
{
    extern __shared__ __align__(16) char smem[];
    const uint32_t sb = smem_u32(smem);
    // Qs: sb..16384 ; Ks stage s: sb+16384+s*8192 ; Vs: sb+40960+s*8192

    const int tid = threadIdx.x;
    const int wid = tid >> 5, lane = tid & 31;
    const int lq = lane >> 2, lr = lane & 3;
    const int lrow = lane & 15, lhi = lane >> 4, l8 = lane & 7, lg = (lane >> 3) & 1;
    const int wrow = wid * 16;
    const int m0 = blockIdx.x * 128;
    const int bh = blockIdx.y, b = bh >> 4, h = bh & 15;

    const __half* Qp = Qg + ((size_t)b * SEQ + m0) * EMB + h * HD;
    const __half* Kp = Kg + (size_t)b * SEQ * EMB + h * HD;
    const __half* Vp = Vg + (size_t)b * SEQ * EMB + h * HD;

    auto issueKV = [&](int kb, int s) {
        const __half* Kr = Kp + (size_t)kb * 64 * EMB;
        const __half* Vr = Vp + (size_t)kb * 64 * EMB;
        uint32_t kb_ = sb + 16384u + s * 8192u, vb_ = sb + 40960u + s * 8192u;
#pragma unroll
        for (int i = 0; i < 2; i++) {
            int q = tid + (i << 8);
            int r = q >> 3, c = q & 7;
            cp16(kb_ + swz(r, c), Kr + (size_t)r * EMB + c * 8);
            cp16(vb_ + swz(r, c), Vr + (size_t)r * EMB + c * 8);
        }
    };

    // group0: Q + KV0 ; group1: KV1
#pragma unroll
    for (int i = 0; i < 4; i++) {
        int q = tid + (i << 8);
        int r = q >> 3, c = q & 7;
        cp16(sb + swz(r, c), Qp + (size_t)r * EMB + c * 8);
    }
    issueKV(0, 0); cp_commit();
    issueKV(1, 1); cp_commit();

    float oacc[8][4];
#pragma unroll
    for (int ni = 0; ni < 8; ni++)
#pragma unroll
        for (int j = 0; j < 4; j++) oacc[ni][j] = 0.f;
    float mrun0 = -1e30f, mrun1 = -1e30f, lrun0 = 0.f, lrun1 = 0.f;
    uint32_t qf[4][4];

    for (int kb = 0; kb < 16; kb++) {
        cp_wait<1>();
        __syncthreads();
        if (kb + 2 < 16) issueKV(kb + 2, (kb + 2) % 3);
        cp_commit();

        if (kb == 0) {
#pragma unroll
            for (int ks = 0; ks < 4; ks++)
                ldsm4(qf[ks], sb + swz(wrow + lrow, ks * 2 + lhi));
        }

        // bias prefetch (hidden under QK mma)
        float2 br0[8], br1[8];
        {
            const float* bp0 = Bias + ((size_t)bh * SEQ + (m0 + wrow + lq)) * SEQ + kb * 64;
            const float* bp1 = bp0 + (size_t)8 * SEQ;
#pragma unroll
            for (int ni = 0; ni < 8; ni++) {
                int c = ni * 8 + (lr << 1);
                br0[ni] = *(const float2*)(bp0 + c);
                br1[ni] = *(const float2*)(bp1 + c);
            }
        }

        const int s = kb % 3;
        const uint32_t kbase = sb + 16384u + s * 8192u;
        const uint32_t vbase = sb + 40960u + s * 8192u;

        // ---- S = Q @ K^T ----
        float sacc[8][4];
#pragma unroll
        for (int ni = 0; ni < 8; ni++)
#pragma unroll
            for (int j = 0; j < 4; j++) sacc[ni][j] = 0.f;
#pragma unroll
        for (int ks = 0; ks < 4; ks++) {
            uint32_t bf[4][4];
#pragma unroll
            for (int np = 0; np < 4; np++)
                ldsm4(bf[np], kbase + swz((np * 2 + lhi) * 8 + l8, ks * 2 + lg));
#pragma unroll
            for (int ni = 0; ni < 8; ni++)
                mma_f16(sacc[ni], qf[ks], &bf[ni >> 1][(ni & 1) * 2]);
        }

        // ---- bias add ----
#pragma unroll
        for (int ni = 0; ni < 8; ni++) {
            sacc[ni][0] += ATTN_CONST * br0[ni].x;
            sacc[ni][1] += ATTN_CONST * br0[ni].y;
            sacc[ni][2] += ATTN_CONST * br1[ni].x;
            sacc[ni][3] += ATTN_CONST * br1[ni].y;
        }

        // ---- online softmax ----
        float mx0 = -1e30f, mx1 = -1e30f;
#pragma unroll
        for (int ni = 0; ni < 8; ni++) {
            mx0 = fmaxf(mx0, fmaxf(sacc[ni][0], sacc[ni][1]));
            mx1 = fmaxf(mx1, fmaxf(sacc[ni][2], sacc[ni][3]));
        }
        mx0 = fmaxf(mx0, __shfl_xor_sync(0xffffffffu, mx0, 1));
        mx0 = fmaxf(mx0, __shfl_xor_sync(0xffffffffu, mx0, 2));
        mx1 = fmaxf(mx1, __shfl_xor_sync(0xffffffffu, mx1, 1));
        mx1 = fmaxf(mx1, __shfl_xor_sync(0xffffffffu, mx1, 2));
        const float mn0 = fmaxf(mrun0, mx0), mn1 = fmaxf(mrun1, mx1);
        const float sc0 = __expf(mrun0 - mn0), sc1 = __expf(mrun1 - mn1);
        float sum0 = 0.f, sum1 = 0.f;
#pragma unroll
        for (int ni = 0; ni < 8; ni++) {
            sacc[ni][0] = __expf(sacc[ni][0] - mn0);
            sacc[ni][1] = __expf(sacc[ni][1] - mn0);
            sacc[ni][2] = __expf(sacc[ni][2] - mn1);
            sacc[ni][3] = __expf(sacc[ni][3] - mn1);
            sum0 += sacc[ni][0] + sacc[ni][1];
            sum1 += sacc[ni][2] + sacc[ni][3];
        }
        sum0 += __shfl_xor_sync(0xffffffffu, sum0, 1);
        sum0 += __shfl_xor_sync(0xffffffffu, sum0, 2);
        sum1 += __shfl_xor_sync(0xffffffffu, sum1, 1);
        sum1 += __shfl_xor_sync(0xffffffffu, sum1, 2);
        lrun0 = lrun0 * sc0 + sum0;
        lrun1 = lrun1 * sc1 + sum1;
        mrun0 = mn0; mrun1 = mn1;
#pragma unroll
        for (int ni = 0; ni < 8; ni++) {
            oacc[ni][0] *= sc0; oacc[ni][1] *= sc0;
            oacc[ni][2] *= sc1; oacc[ni][3] *= sc1;
        }

        // ---- P -> fp16 regs (C-frag == A-frag) ----
        uint32_t pl[8], pu[8];
#pragma unroll
        for (int ni = 0; ni < 8; ni++) {
            pl[ni] = h2u(__floats2half2_rn(sacc[ni][0], sacc[ni][1]));
            pu[ni] = h2u(__floats2half2_rn(sacc[ni][2], sacc[ni][3]));
        }

        // ---- O += P @ V (V via ldmatrix.trans) ----
#pragma unroll
        for (int ks = 0; ks < 4; ks++) {
            uint32_t a[4] = {pl[2 * ks], pu[2 * ks], pl[2 * ks + 1], pu[2 * ks + 1]};
            uint32_t bf[4][4];
#pragma unroll
            for (int np = 0; np < 4; np++)
                ldsm4t(bf[np], vbase + swz(ks * 16 + lg * 8 + l8, np * 2 + lhi));
#pragma unroll
            for (int ni = 0; ni < 8; ni++)
                mma_f16(oacc[ni], a, &bf[ni >> 1][(ni & 1) * 2]);
        }
    }

    // ---- epilogue: normalize + fp16 store ----
    const float inv0 = 1.0f / lrun0, inv1 = 1.0f / lrun1;
    __half* Op0 = Og + ((size_t)b * SEQ + (m0 + wrow + lq)) * EMB + h * HD;
    __half* Op1 = Op0 + (size_t)8 * EMB;
#pragma unroll
    for (int ni = 0; ni < 8; ni++) {
        int c = ni * 8 + (lr << 1);
        *(__half2*)(Op0 + c) = __floats2half2_rn(oacc[ni][0] * inv0, oacc[ni][1] * inv0);
        *(__half2*)(Op1 + c) = __floats2half2_rn(oacc[ni][2] * inv1, oacc[ni][3] * inv1);
    }
}

// ---------------- launcher ---------------------------------------------------
extern "C" void kernel_launch(void* const* d_in, const int* in_sizes, int n_in,
                              void* d_out, int out_size)
{
    const float* hidden = (const float*)d_in[0];
    const float* attn_b = (const float*)d_in[1];
    const float* Wq = (const float*)d_in[2];
    const float* bq = (const float*)d_in[3];
    const float* Wk = (const float*)d_in[4];
    const float* bk = (const float*)d_in[5];
    const float* Wv = (const float*)d_in[6];
    const float* bv = (const float*)d_in[7];
    const float* Wo = (const float*)d_in[8];
    const float* bo = (const float*)d_in[9];
    float* out = (float*)d_out;

    __half *h16, *w16, *q16, *k16, *v16, *a16;
    cudaGetSymbolAddress((void**)&h16, g_h16);
    cudaGetSymbolAddress((void**)&w16, g_w16);
    cudaGetSymbolAddress((void**)&q16, g_q16);
    cudaGetSymbolAddress((void**)&k16, g_k16);
    cudaGetSymbolAddress((void**)&v16, g_v16);
    cudaGetSymbolAddress((void**)&a16, g_a16);

    const int GEMM_SMEM = 98304;   // 3 stages x (16KB A + 16KB B)
    const int FLASH_SMEM = 65536;  // Q 16KB + 3x(8KB K + 8KB V)
    cudaFuncSetAttribute(hgemm<true>, cudaFuncAttributeMaxDynamicSharedMemorySize, GEMM_SMEM);
    cudaFuncSetAttribute(hgemm<false>, cudaFuncAttributeMaxDynamicSharedMemorySize, GEMM_SMEM);
    cudaFuncSetAttribute(flash16, cudaFuncAttributeMaxDynamicSharedMemorySize, FLASH_SMEM);

    // f32 -> fp16 conversions
    f32to16<<<4096, 256>>>((const float4*)hidden, (uint2*)h16, 1048576);
    f32to16<<<1024, 256>>>((const float4*)Wq, (uint2*)(w16 + 0 * 1048576), 262144);
    f32to16<<<1024, 256>>>((const float4*)Wk, (uint2*)(w16 + 1 * 1048576), 262144);
    f32to16<<<1024, 256>>>((const float4*)Wv, (uint2*)(w16 + 2 * 1048576), 262144);
    f32to16<<<1024, 256>>>((const float4*)Wo, (uint2*)(w16 + 3 * 1048576), 262144);

    // QKV projections (fp16 out; q pre-scaled)
    hgemm<true><<<dim3(EMB / 128, (BSZ * SEQ) / 128, 3), 512, GEMM_SMEM>>>(
        h16, w16, w16 + 1048576, w16 + 2 * 1048576,
        bq, bk, bv, q16, k16, v16, SCALING);

    // fused attention (fp16 in/out)
    flash16<<<dim3(SEQ / 128, BSZ * NH), 256, FLASH_SMEM>>>(q16, k16, v16, attn_b, a16);

    // output projection (f32 out)
    hgemm<false><<<dim3(EMB / 128, (BSZ * SEQ) / 128, 1), 512, GEMM_SMEM>>>(
        a16, w16 + 3 * 1048576, w16 + 3 * 1048576, w16 + 3 * 1048576,
        bo, bo, bo, out, out, out, 1.0f);
}

// round 7
// speedup vs baseline: 6.4745x; 1.1799x over previous
#include <cuda_runtime.h>
#include <cuda_fp16.h>
#include <cstdint>
#include <math.h>

#define SEQ 1024
#define EMB 1024
#define BSZ 4
#define NH  16
#define HD  64
#define SCALING 0.125f
#define ATTN_CONST 3.032639477052158f
#define LOG2E 1.44269504088896340736f

// ---------------- fp16 scratch (device globals) -----------------------------
__device__ __half g_h16[BSZ * SEQ * EMB];
__device__ __half g_w16[4][EMB * EMB];
__device__ __half g_q16[BSZ * SEQ * EMB];
__device__ __half g_k16[BSZ * SEQ * EMB];
__device__ __half g_v16[BSZ * SEQ * EMB];
__device__ __half g_a16[BSZ * SEQ * EMB];

// ---------------- helpers ----------------------------------------------------
__device__ __forceinline__ uint32_t h2u(__half2 h) { return *(uint32_t*)&h; }
__device__ __forceinline__ uint32_t smem_u32(const void* p) {
    uint32_t a;
    asm("{ .reg .u64 t; cvta.to.shared.u64 t, %1; cvt.u32.u64 %0, t; }" : "=r"(a) : "l"(p));
    return a;
}
__device__ __forceinline__ void cp16(uint32_t dst, const void* src) {
    asm volatile("cp.async.ca.shared.global [%0], [%1], 16;" :: "r"(dst), "l"(src));
}
__device__ __forceinline__ void cp_commit() { asm volatile("cp.async.commit_group;" ::: "memory"); }
template <int N>
__device__ __forceinline__ void cp_wait() {
    asm volatile("cp.async.wait_group %0;" :: "n"(N) : "memory");
}
__device__ __forceinline__ void ldsm4(uint32_t* r, uint32_t addr) {
    asm volatile("ldmatrix.sync.aligned.m8n8.x4.shared.b16 {%0,%1,%2,%3}, [%4];"
                 : "=r"(r[0]), "=r"(r[1]), "=r"(r[2]), "=r"(r[3]) : "r"(addr));
}
__device__ __forceinline__ void ldsm4t(uint32_t* r, uint32_t addr) {
    asm volatile("ldmatrix.sync.aligned.m8n8.x4.trans.shared.b16 {%0,%1,%2,%3}, [%4];"
                 : "=r"(r[0]), "=r"(r[1]), "=r"(r[2]), "=r"(r[3]) : "r"(addr));
}
// Swizzle<3,3,3>: rows of 64 halves (128B), 8 chunks of 16B; byte offset in tile
__device__ __forceinline__ uint32_t swz(int r, int chunk) {
    return (uint32_t)(r * 128 + ((chunk ^ (r & 7)) << 4));
}
__device__ __forceinline__ void mma_f16(float* c, const uint32_t* a, const uint32_t* b) {
    asm volatile(
        "mma.sync.aligned.m16n8k16.row.col.f32.f16.f16.f32 "
        "{%0,%1,%2,%3}, {%4,%5,%6,%7}, {%8,%9}, {%0,%1,%2,%3};"
        : "+f"(c[0]), "+f"(c[1]), "+f"(c[2]), "+f"(c[3])
        : "r"(a[0]), "r"(a[1]), "r"(a[2]), "r"(a[3]), "r"(b[0]), "r"(b[1]));
}
__device__ __forceinline__ float ex2(float x) {
    float y;
    asm("ex2.approx.f32 %0, %1;" : "=f"(y) : "f"(x));
    return y;
}

// ---------------- fused f32 -> fp16 convert (all 5 tensors, 1 launch) --------
__global__ void __launch_bounds__(256)
conv_all(const float4* __restrict__ hid,
         const float4* __restrict__ wq, const float4* __restrict__ wk,
         const float4* __restrict__ wv, const float4* __restrict__ wo,
         uint2* __restrict__ h16d, uint2* __restrict__ w16d)
{
    int i = blockIdx.x * blockDim.x + threadIdx.x;   // 2097152 total
    float4 v;
    uint2* dst;
    if (i < 1048576) {
        v = hid[i];
        dst = h16d + i;
    } else {
        int j = i - 1048576;
        int w = j >> 18;
        int o = j & 262143;
        const float4* s = (w == 0) ? wq : (w == 1) ? wk : (w == 2) ? wv : wo;
        v = s[o];
        dst = w16d + j;
    }
    *dst = make_uint2(h2u(__floats2half2_rn(v.x, v.y)),
                      h2u(__floats2half2_rn(v.z, v.w)));
}

// ============ fp16 GEMM: C = (A @ W^T + b) * scale ==========================
// BM=128, BN=256, BK=64, 256 threads (8 warps, 2m x 4n, warp tile 64x64).
// 3-stage cp.async + ldmatrix. OUT16 -> fp16 C, else f32 C.
template <bool OUT16>
__global__ void __launch_bounds__(256, 1)
hgemm(const __half* __restrict__ A,
      const __half* __restrict__ W0, const __half* __restrict__ W1,
      const __half* __restrict__ W2,
      const float* __restrict__ b0, const float* __restrict__ b1,
      const float* __restrict__ b2,
      void* __restrict__ C0, void* __restrict__ C1, void* __restrict__ C2,
      float scale0)
{
    extern __shared__ __align__(16) char smem[];
    const uint32_t sb = smem_u32(smem);
    // A stage s: sb + s*16384 (48KB) ; W stage s: sb + 49152 + s*32768 (96KB)

    const int z = blockIdx.z;
    const __half* W = (z == 0) ? W0 : (z == 1) ? W1 : W2;
    const float* bias = (z == 0) ? b0 : (z == 1) ? b1 : b2;
    void* C = (z == 0) ? C0 : (z == 1) ? C1 : C2;
    const float scale = (z == 0) ? scale0 : 1.0f;

    const int tid = threadIdx.x;
    const int wid = tid >> 5, lane = tid & 31;
    const int lq = lane >> 2, lr = lane & 3;
    const int lrow = lane & 15, lhi = lane >> 4, l8 = lane & 7, lg = (lane >> 3) & 1;
    const int warp_m = (wid & 1) * 64, warp_n = (wid >> 1) * 64;
    const int m0 = blockIdx.y * 128, n0 = blockIdx.x * 256;

    float acc[4][8][4];
#pragma unroll
    for (int mi = 0; mi < 4; mi++)
#pragma unroll
        for (int ni = 0; ni < 8; ni++)
#pragma unroll
            for (int j = 0; j < 4; j++) acc[mi][ni][j] = 0.f;

    auto issue = [&](int kk, int s) {
        const __half* Ag = A + (size_t)m0 * EMB + kk * 64;
        const __half* Wg = W + (size_t)n0 * EMB + kk * 64;
        uint32_t ab = sb + s * 16384u, bb = sb + 49152u + s * 32768u;
#pragma unroll
        for (int i = 0; i < 4; i++) {
            int q = tid + (i << 8);
            int r = q >> 3, c = q & 7;
            cp16(ab + swz(r, c), Ag + (size_t)r * EMB + c * 8);
        }
#pragma unroll
        for (int i = 0; i < 8; i++) {
            int q = tid + (i << 8);
            int r = q >> 3, c = q & 7;
            cp16(bb + swz(r, c), Wg + (size_t)r * EMB + c * 8);
        }
    };
    issue(0, 0); cp_commit();
    issue(1, 1); cp_commit();

    for (int kk = 0; kk < 16; kk++) {
        cp_wait<1>();
        __syncthreads();
        if (kk + 2 < 16) issue(kk + 2, (kk + 2) % 3);
        cp_commit();

        const int s = kk % 3;
        const uint32_t ab = sb + s * 16384u, bb = sb + 49152u + s * 32768u;
#pragma unroll
        for (int ks = 0; ks < 4; ks++) {
            uint32_t af[4][4], bf[4][4];
#pragma unroll
            for (int mi = 0; mi < 4; mi++)
                ldsm4(af[mi], ab + swz(warp_m + mi * 16 + lrow, ks * 2 + lhi));
#pragma unroll
            for (int np = 0; np < 4; np++)
                ldsm4(bf[np], bb + swz(warp_n + (np * 2 + lhi) * 8 + l8, ks * 2 + lg));
#pragma unroll
            for (int mi = 0; mi < 4; mi++)
#pragma unroll
                for (int ni = 0; ni < 8; ni++)
                    mma_f16(acc[mi][ni], af[mi], &bf[ni >> 1][(ni & 1) * 2]);
        }
    }

#pragma unroll
    for (int mi = 0; mi < 4; mi++) {
#pragma unroll
        for (int ni = 0; ni < 8; ni++) {
            int row = m0 + warp_m + mi * 16 + lq;
            int col = n0 + warp_n + ni * 8 + (lr << 1);
            float2 bv = *(const float2*)(bias + col);
#pragma unroll
            for (int hh = 0; hh < 2; hh++) {
                int r = row + hh * 8;
                float x = (acc[mi][ni][hh * 2 + 0] + bv.x) * scale;
                float y = (acc[mi][ni][hh * 2 + 1] + bv.y) * scale;
                if (OUT16)
                    *(__half2*)((__half*)C + (size_t)r * EMB + col) = __floats2half2_rn(x, y);
                else
                    *(float2*)((float*)C + (size_t)r * EMB + col) = make_float2(x, y);
            }
        }
    }
}

// ================= fused flash attention (fp16 in/out, exp2 domain) =========
// Q pre-scaled by SCALING*LOG2E; bias scaled by ATTN_CONST*LOG2E; softmax = 2^x.
__global__ void __launch_bounds__(256, 1)
flash16(const __half* __restrict__ Qg, const __half* __restrict__ Kg,
        const __half* __restrict__ Vg, const float* __restrict__ Bias,
        __half* __restrict__ Og)
{
    extern __shared__ __align__(16) char smem[];
    const uint32_t sb = smem_u32(smem);
    // Qs: sb..16384 ; Ks stage s: sb+16384+s*8192 ; Vs: sb+40960+s*8192

    const int tid = threadIdx.x;
    const int wid = tid >> 5, lane = tid & 31;
    const int lq = lane >> 2, lr = lane & 3;
    const int lrow = lane & 15, lhi = lane >> 4, l8 = lane & 7, lg = (lane >> 3) & 1;
    const int wrow = wid * 16;
    const int m0 = blockIdx.x * 128;
    const int bh = blockIdx.y, b = bh >> 4, h = bh & 15;

    const __half* Qp = Qg + ((size_t)b * SEQ + m0) * EMB + h * HD;
    const __half* Kp = Kg + (size_t)b * SEQ * EMB + h * HD;
    const __half* Vp = Vg + (size_t)b * SEQ * EMB + h * HD;
    const float BC = ATTN_CONST * LOG2E;

    auto issueKV = [&](int kb, int s) {
        const __half* Kr = Kp + (size_t)kb * 64 * EMB;
        const __half* Vr = Vp + (size_t)kb * 64 * EMB;
        uint32_t kb_ = sb + 16384u + s * 8192u, vb_ = sb + 40960u + s * 8192u;
#pragma unroll
        for (int i = 0; i < 2; i++) {
            int q = tid + (i << 8);
            int r = q >> 3, c = q & 7;
            cp16(kb_ + swz(r, c), Kr + (size_t)r * EMB + c * 8);
            cp16(vb_ + swz(r, c), Vr + (size_t)r * EMB + c * 8);
        }
    };

#pragma unroll
    for (int i = 0; i < 4; i++) {
        int q = tid + (i << 8);
        int r = q >> 3, c = q & 7;
        cp16(sb + swz(r, c), Qp + (size_t)r * EMB + c * 8);
    }
    issueKV(0, 0); cp_commit();
    issueKV(1, 1); cp_commit();

    float oacc[8][4];
#pragma unroll
    for (int ni = 0; ni < 8; ni++)
#pragma unroll
        for (int j = 0; j < 4; j++) oacc[ni][j] = 0.f;
    float mrun0 = -1e30f, mrun1 = -1e30f, lrun0 = 0.f, lrun1 = 0.f;
    uint32_t qf[4][4];

    for (int kb = 0; kb < 16; kb++) {
        cp_wait<1>();
        __syncthreads();
        if (kb + 2 < 16) issueKV(kb + 2, (kb + 2) % 3);
        cp_commit();

        if (kb == 0) {
#pragma unroll
            for (int ks = 0; ks < 4; ks++)
                ldsm4(qf[ks], sb + swz(wrow + lrow, ks * 2 + lhi));
        }

        // bias prefetch (hidden under QK mma)
        float2 br0[8], br1[8];
        {
            const float* bp0 = Bias + ((size_t)bh * SEQ + (m0 + wrow + lq)) * SEQ + kb * 64;
            const float* bp1 = bp0 + (size_t)8 * SEQ;
#pragma unroll
            for (int ni = 0; ni < 8; ni++) {
                int c = ni * 8 + (lr << 1);
                br0[ni] = *(const float2*)(bp0 + c);
                br1[ni] = *(const float2*)(bp1 + c);
            }
        }

        const int s = kb % 3;
        const uint32_t kbase = sb + 16384u + s * 8192u;
        const uint32_t vbase = sb + 40960u + s * 8192u;

        // ---- S = Q @ K^T (log2 domain) ----
        float sacc[8][4];
#pragma unroll
        for (int ni = 0; ni < 8; ni++)
#pragma unroll
            for (int j = 0; j < 4; j++) sacc[ni][j] = 0.f;
#pragma unroll
        for (int ks = 0; ks < 4; ks++) {
            uint32_t bf[4][4];
#pragma unroll
            for (int np = 0; np < 4; np++)
                ldsm4(bf[np], kbase + swz((np * 2 + lhi) * 8 + l8, ks * 2 + lg));
#pragma unroll
            for (int ni = 0; ni < 8; ni++)
                mma_f16(sacc[ni], qf[ks], &bf[ni >> 1][(ni & 1) * 2]);
        }

        // ---- bias add ----
#pragma unroll
        for (int ni = 0; ni < 8; ni++) {
            sacc[ni][0] += BC * br0[ni].x;
            sacc[ni][1] += BC * br0[ni].y;
            sacc[ni][2] += BC * br1[ni].x;
            sacc[ni][3] += BC * br1[ni].y;
        }

        // ---- online softmax (base-2) ----
        float mx0 = -1e30f, mx1 = -1e30f;
#pragma unroll
        for (int ni = 0; ni < 8; ni++) {
            mx0 = fmaxf(mx0, fmaxf(sacc[ni][0], sacc[ni][1]));
            mx1 = fmaxf(mx1, fmaxf(sacc[ni][2], sacc[ni][3]));
        }
        mx0 = fmaxf(mx0, __shfl_xor_sync(0xffffffffu, mx0, 1));
        mx0 = fmaxf(mx0, __shfl_xor_sync(0xffffffffu, mx0, 2));
        mx1 = fmaxf(mx1, __shfl_xor_sync(0xffffffffu, mx1, 1));
        mx1 = fmaxf(mx1, __shfl_xor_sync(0xffffffffu, mx1, 2));
        const float mn0 = fmaxf(mrun0, mx0), mn1 = fmaxf(mrun1, mx1);
        const float sc0 = ex2(mrun0 - mn0), sc1 = ex2(mrun1 - mn1);
        float sum0 = 0.f, sum1 = 0.f;
#pragma unroll
        for (int ni = 0; ni < 8; ni++) {
            sacc[ni][0] = ex2(sacc[ni][0] - mn0);
            sacc[ni][1] = ex2(sacc[ni][1] - mn0);
            sacc[ni][2] = ex2(sacc[ni][2] - mn1);
            sacc[ni][3] = ex2(sacc[ni][3] - mn1);
            sum0 += sacc[ni][0] + sacc[ni][1];
            sum1 += sacc[ni][2] + sacc[ni][3];
        }
        sum0 += __shfl_xor_sync(0xffffffffu, sum0, 1);
        sum0 += __shfl_xor_sync(0xffffffffu, sum0, 2);
        sum1 += __shfl_xor_sync(0xffffffffu, sum1, 1);
        sum1 += __shfl_xor_sync(0xffffffffu, sum1, 2);
        lrun0 = lrun0 * sc0 + sum0;
        lrun1 = lrun1 * sc1 + sum1;
        mrun0 = mn0; mrun1 = mn1;
#pragma unroll
        for (int ni = 0; ni < 8; ni++) {
            oacc[ni][0] *= sc0; oacc[ni][1] *= sc0;
            oacc[ni][2] *= sc1; oacc[ni][3] *= sc1;
        }

        // ---- P -> fp16 regs (C-frag == A-frag) ----
        uint32_t pl[8], pu[8];
#pragma unroll
        for (int ni = 0; ni < 8; ni++) {
            pl[ni] = h2u(__floats2half2_rn(sacc[ni][0], sacc[ni][1]));
            pu[ni] = h2u(__floats2half2_rn(sacc[ni][2], sacc[ni][3]));
        }

        // ---- O += P @ V (V via ldmatrix.trans) ----
#pragma unroll
        for (int ks = 0; ks < 4; ks++) {
            uint32_t a[4] = {pl[2 * ks], pu[2 * ks], pl[2 * ks + 1], pu[2 * ks + 1]};
            uint32_t bf[4][4];
#pragma unroll
            for (int np = 0; np < 4; np++)
                ldsm4t(bf[np], vbase + swz(ks * 16 + lg * 8 + l8, np * 2 + lhi));
#pragma unroll
            for (int ni = 0; ni < 8; ni++)
                mma_f16(oacc[ni], a, &bf[ni >> 1][(ni & 1) * 2]);
        }
    }

    // ---- epilogue: normalize + fp16 store ----
    const float inv0 = 1.0f / lrun0, inv1 = 1.0f / lrun1;
    __half* Op0 = Og + ((size_t)b * SEQ + (m0 + wrow + lq)) * EMB + h * HD;
    __half* Op1 = Op0 + (size_t)8 * EMB;
#pragma unroll
    for (int ni = 0; ni < 8; ni++) {
        int c = ni * 8 + (lr << 1);
        *(__half2*)(Op0 + c) = __floats2half2_rn(oacc[ni][0] * inv0, oacc[ni][1] * inv0);
        *(__half2*)(Op1 + c) = __floats2half2_rn(oacc[ni][2] * inv1, oacc[ni][3] * inv1);
    }
}

// ---------------- launcher ---------------------------------------------------
extern "C" void kernel_launch(void* const* d_in, const int* in_sizes, int n_in,
                              void* d_out, int out_size)
{
    const float* hidden = (const float*)d_in[0];
    const float* attn_b = (const float*)d_in[1];
    const float* Wq = (const float*)d_in[2];
    const float* bq = (const float*)d_in[3];
    const float* Wk = (const float*)d_in[4];
    const float* bk = (const float*)d_in[5];
    const float* Wv = (const float*)d_in[6];
    const float* bv = (const float*)d_in[7];
    const float* Wo = (const float*)d_in[8];
    const float* bo = (const float*)d_in[9];
    float* out = (float*)d_out;

    __half *h16, *w16, *q16, *k16, *v16, *a16;
    cudaGetSymbolAddress((void**)&h16, g_h16);
    cudaGetSymbolAddress((void**)&w16, g_w16);
    cudaGetSymbolAddress((void**)&q16, g_q16);
    cudaGetSymbolAddress((void**)&k16, g_k16);
    cudaGetSymbolAddress((void**)&v16, g_v16);
    cudaGetSymbolAddress((void**)&a16, g_a16);

    const int GEMM_SMEM = 147456;  // 3 x (16KB A + 32KB B)
    const int FLASH_SMEM = 65536;  // Q 16KB + 3 x (8KB K + 8KB V)
    cudaFuncSetAttribute(hgemm<true>, cudaFuncAttributeMaxDynamicSharedMemorySize, GEMM_SMEM);
    cudaFuncSetAttribute(hgemm<false>, cudaFuncAttributeMaxDynamicSharedMemorySize, GEMM_SMEM);
    cudaFuncSetAttribute(flash16, cudaFuncAttributeMaxDynamicSharedMemorySize, FLASH_SMEM);

    // fused f32 -> fp16 conversions (single launch)
    conv_all<<<8192, 256>>>((const float4*)hidden, (const float4*)Wq,
                            (const float4*)Wk, (const float4*)Wv, (const float4*)Wo,
                            (uint2*)h16, (uint2*)w16);

    // QKV projections (fp16 out; q pre-scaled by SCALING*LOG2E for exp2 softmax)
    hgemm<true><<<dim3(EMB / 256, (BSZ * SEQ) / 128, 3), 256, GEMM_SMEM>>>(
        h16, w16, w16 + 1048576, w16 + 2 * 1048576,
        bq, bk, bv, q16, k16, v16, SCALING * LOG2E);

    // fused attention (fp16 in/out)
    flash16<<<dim3(SEQ / 128, BSZ * NH), 256, FLASH_SMEM>>>(q16, k16, v16, attn_b, a16);

    // output projection (f32 out)
    hgemm<false><<<dim3(EMB / 256, (BSZ * SEQ) / 128, 1), 256, GEMM_SMEM>>>(
        a16, w16 + 3 * 1048576, w16 + 3 * 1048576, w16 + 3 * 1048576,
        bo, bo, bo, out, out, out, 1.0f);
}

// round 8
// speedup vs baseline: 6.7117x; 1.0366x over previous
#include <cuda_runtime.h>
#include <cuda_fp16.h>
#include <cstdint>
#include <math.h>

#define SEQ 1024
#define EMB 1024
#define BSZ 4
#define NH  16
#define HD  64
#define SCALING 0.125f
#define ATTN_CONST 3.032639477052158f
#define LOG2E 1.44269504088896340736f

// ---------------- fp16 scratch (device globals) -----------------------------
__device__ __half g_h16[BSZ * SEQ * EMB];
__device__ __half g_w16[4][EMB * EMB];
__device__ __half g_q16[BSZ * SEQ * EMB];
__device__ __half g_k16[BSZ * SEQ * EMB];
__device__ __half g_v16[BSZ * SEQ * EMB];
__device__ __half g_a16[BSZ * SEQ * EMB];

// ---------------- helpers ----------------------------------------------------
__device__ __forceinline__ uint32_t h2u(__half2 h) { return *(uint32_t*)&h; }
__device__ __forceinline__ uint32_t smem_u32(const void* p) {
    uint32_t a;
    asm("{ .reg .u64 t; cvta.to.shared.u64 t, %1; cvt.u32.u64 %0, t; }" : "=r"(a) : "l"(p));
    return a;
}
__device__ __forceinline__ void cp16(uint32_t dst, const void* src) {
    asm volatile("cp.async.ca.shared.global [%0], [%1], 16;" :: "r"(dst), "l"(src));
}
__device__ __forceinline__ void cp_commit() { asm volatile("cp.async.commit_group;" ::: "memory"); }
template <int N>
__device__ __forceinline__ void cp_wait() {
    asm volatile("cp.async.wait_group %0;" :: "n"(N) : "memory");
}
__device__ __forceinline__ void ldsm4(uint32_t* r, uint32_t addr) {
    asm volatile("ldmatrix.sync.aligned.m8n8.x4.shared.b16 {%0,%1,%2,%3}, [%4];"
                 : "=r"(r[0]), "=r"(r[1]), "=r"(r[2]), "=r"(r[3]) : "r"(addr));
}
__device__ __forceinline__ void ldsm4t(uint32_t* r, uint32_t addr) {
    asm volatile("ldmatrix.sync.aligned.m8n8.x4.trans.shared.b16 {%0,%1,%2,%3}, [%4];"
                 : "=r"(r[0]), "=r"(r[1]), "=r"(r[2]), "=r"(r[3]) : "r"(addr));
}
// Swizzle<3,3,3>: rows of 64 halves (128B), 8 chunks of 16B; byte offset in tile
__device__ __forceinline__ uint32_t swz(int r, int chunk) {
    return (uint32_t)(r * 128 + ((chunk ^ (r & 7)) << 4));
}
__device__ __forceinline__ void mma_f16(float* c, const uint32_t* a, const uint32_t* b) {
    asm volatile(
        "mma.sync.aligned.m16n8k16.row.col.f32.f16.f16.f32 "
        "{%0,%1,%2,%3}, {%4,%5,%6,%7}, {%8,%9}, {%0,%1,%2,%3};"
        : "+f"(c[0]), "+f"(c[1]), "+f"(c[2]), "+f"(c[3])
        : "r"(a[0]), "r"(a[1]), "r"(a[2]), "r"(a[3]), "r"(b[0]), "r"(b[1]));
}
__device__ __forceinline__ float ex2(float x) {
    float y;
    asm("ex2.approx.f32 %0, %1;" : "=f"(y) : "f"(x));
    return y;
}

// ---------------- fused f32 -> fp16 convert (all 5 tensors, 1 launch) --------
__global__ void __launch_bounds__(256)
conv_all(const float4* __restrict__ hid,
         const float4* __restrict__ wq, const float4* __restrict__ wk,
         const float4* __restrict__ wv, const float4* __restrict__ wo,
         uint2* __restrict__ h16d, uint2* __restrict__ w16d)
{
    int i = blockIdx.x * blockDim.x + threadIdx.x;   // 2097152 total
    float4 v;
    uint2* dst;
    if (i < 1048576) {
        v = hid[i];
        dst = h16d + i;
    } else {
        int j = i - 1048576;
        int w = j >> 18;
        int o = j & 262143;
        const float4* s = (w == 0) ? wq : (w == 1) ? wk : (w == 2) ? wv : wo;
        v = s[o];
        dst = w16d + j;
    }
    *dst = make_uint2(h2u(__floats2half2_rn(v.x, v.y)),
                      h2u(__floats2half2_rn(v.z, v.w)));
}

// ============ fp16 GEMM: C = (A @ W^T + b) * scale ==========================
// BM=128, BN=256, BK=64, 256 threads (8 warps, 2m x 4n, warp tile 64x64).
// 3-stage cp.async + ldmatrix. OUT16 -> fp16 C, else f32 C.
template <bool OUT16>
__global__ void __launch_bounds__(256, 1)
hgemm(const __half* __restrict__ A,
      const __half* __restrict__ W0, const __half* __restrict__ W1,
      const __half* __restrict__ W2,
      const float* __restrict__ b0, const float* __restrict__ b1,
      const float* __restrict__ b2,
      void* __restrict__ C0, void* __restrict__ C1, void* __restrict__ C2,
      float scale0)
{
    extern __shared__ __align__(16) char smem[];
    const uint32_t sb = smem_u32(smem);

    const int z = blockIdx.z;
    const __half* W = (z == 0) ? W0 : (z == 1) ? W1 : W2;
    const float* bias = (z == 0) ? b0 : (z == 1) ? b1 : b2;
    void* C = (z == 0) ? C0 : (z == 1) ? C1 : C2;
    const float scale = (z == 0) ? scale0 : 1.0f;

    const int tid = threadIdx.x;
    const int wid = tid >> 5, lane = tid & 31;
    const int lq = lane >> 2, lr = lane & 3;
    const int lrow = lane & 15, lhi = lane >> 4, l8 = lane & 7, lg = (lane >> 3) & 1;
    const int warp_m = (wid & 1) * 64, warp_n = (wid >> 1) * 64;
    const int m0 = blockIdx.y * 128, n0 = blockIdx.x * 256;

    float acc[4][8][4];
#pragma unroll
    for (int mi = 0; mi < 4; mi++)
#pragma unroll
        for (int ni = 0; ni < 8; ni++)
#pragma unroll
            for (int j = 0; j < 4; j++) acc[mi][ni][j] = 0.f;

    auto issue = [&](int kk, int s) {
        const __half* Ag = A + (size_t)m0 * EMB + kk * 64;
        const __half* Wg = W + (size_t)n0 * EMB + kk * 64;
        uint32_t ab = sb + s * 16384u, bb = sb + 49152u + s * 32768u;
#pragma unroll
        for (int i = 0; i < 4; i++) {
            int q = tid + (i << 8);
            int r = q >> 3, c = q & 7;
            cp16(ab + swz(r, c), Ag + (size_t)r * EMB + c * 8);
        }
#pragma unroll
        for (int i = 0; i < 8; i++) {
            int q = tid + (i << 8);
            int r = q >> 3, c = q & 7;
            cp16(bb + swz(r, c), Wg + (size_t)r * EMB + c * 8);
        }
    };
    issue(0, 0); cp_commit();
    issue(1, 1); cp_commit();

    for (int kk = 0; kk < 16; kk++) {
        cp_wait<1>();
        __syncthreads();
        if (kk + 2 < 16) issue(kk + 2, (kk + 2) % 3);
        cp_commit();

        const int s = kk % 3;
        const uint32_t ab = sb + s * 16384u, bb = sb + 49152u + s * 32768u;
#pragma unroll
        for (int ks = 0; ks < 4; ks++) {
            uint32_t af[4][4], bf[4][4];
#pragma unroll
            for (int mi = 0; mi < 4; mi++)
                ldsm4(af[mi], ab + swz(warp_m + mi * 16 + lrow, ks * 2 + lhi));
#pragma unroll
            for (int np = 0; np < 4; np++)
                ldsm4(bf[np], bb + swz(warp_n + (np * 2 + lhi) * 8 + l8, ks * 2 + lg));
#pragma unroll
            for (int mi = 0; mi < 4; mi++)
#pragma unroll
                for (int ni = 0; ni < 8; ni++)
                    mma_f16(acc[mi][ni], af[mi], &bf[ni >> 1][(ni & 1) * 2]);
        }
    }

#pragma unroll
    for (int mi = 0; mi < 4; mi++) {
#pragma unroll
        for (int ni = 0; ni < 8; ni++) {
            int row = m0 + warp_m + mi * 16 + lq;
            int col = n0 + warp_n + ni * 8 + (lr << 1);
            float2 bv = *(const float2*)(bias + col);
#pragma unroll
            for (int hh = 0; hh < 2; hh++) {
                int r = row + hh * 8;
                float x = (acc[mi][ni][hh * 2 + 0] + bv.x) * scale;
                float y = (acc[mi][ni][hh * 2 + 1] + bv.y) * scale;
                if (OUT16)
                    *(__half2*)((__half*)C + (size_t)r * EMB + col) = __floats2half2_rn(x, y);
                else
                    *(float2*)((float*)C + (size_t)r * EMB + col) = make_float2(x, y);
            }
        }
    }
}

// ================= fused flash attention (fp16, exp2, async bias) ===========
// Q pre-scaled by SCALING*LOG2E; bias scaled by ATTN_CONST*LOG2E; softmax = 2^x.
// K/V/bias all flow through a 3-stage cp.async pipeline (2 iters ahead).
// SMEM: Q 16KB | K 3x8KB | V 3x8KB | bias 3x34KB (f32, rows padded to 272B)
#define BIAS_ROW 68   // floats per row (64 + 4 pad) -> conflict-free float2 LDS
__global__ void __launch_bounds__(256, 1)
flash16(const __half* __restrict__ Qg, const __half* __restrict__ Kg,
        const __half* __restrict__ Vg, const float* __restrict__ Bias,
        __half* __restrict__ Og)
{
    extern __shared__ __align__(16) char smem[];
    const uint32_t sb = smem_u32(smem);
    const uint32_t KBASE = sb + 16384u;
    const uint32_t VBASE = sb + 40960u;
    const uint32_t BBASE = sb + 65536u;          // 3 stages x 34816 B

    const int tid = threadIdx.x;
    const int wid = tid >> 5, lane = tid & 31;
    const int lq = lane >> 2, lr = lane & 3;
    const int lrow = lane & 15, lhi = lane >> 4, l8 = lane & 7, lg = (lane >> 3) & 1;
    const int wrow = wid * 16;
    const int m0 = blockIdx.x * 128;
    const int bh = blockIdx.y, b = bh >> 4, h = bh & 15;

    const __half* Qp = Qg + ((size_t)b * SEQ + m0) * EMB + h * HD;
    const __half* Kp = Kg + (size_t)b * SEQ * EMB + h * HD;
    const __half* Vp = Vg + (size_t)b * SEQ * EMB + h * HD;
    const float* Bp = Bias + ((size_t)bh * SEQ + m0) * SEQ;
    const float BC = ATTN_CONST * LOG2E;

    auto issueKVB = [&](int kb, int s) {
        const __half* Kr = Kp + (size_t)kb * 64 * EMB;
        const __half* Vr = Vp + (size_t)kb * 64 * EMB;
        uint32_t kb_ = KBASE + s * 8192u, vb_ = VBASE + s * 8192u;
#pragma unroll
        for (int i = 0; i < 2; i++) {
            int q = tid + (i << 8);
            int r = q >> 3, c = q & 7;
            cp16(kb_ + swz(r, c), Kr + (size_t)r * EMB + c * 8);
            cp16(vb_ + swz(r, c), Vr + (size_t)r * EMB + c * 8);
        }
        // bias tile 128 x 64 f32: 2048 16B-chunks
        uint32_t bb_ = BBASE + s * 34816u;
        const float* Br = Bp + kb * 64;
#pragma unroll
        for (int i = 0; i < 8; i++) {
            int q = tid + (i << 8);
            int r = q >> 4, c = q & 15;
            cp16(bb_ + (uint32_t)(r * (BIAS_ROW * 4) + c * 16),
                 Br + (size_t)r * SEQ + c * 4);
        }
    };

    // Q tile + stage 0/1 prefetch
#pragma unroll
    for (int i = 0; i < 4; i++) {
        int q = tid + (i << 8);
        int r = q >> 3, c = q & 7;
        cp16(sb + swz(r, c), Qp + (size_t)r * EMB + c * 8);
    }
    issueKVB(0, 0); cp_commit();
    issueKVB(1, 1); cp_commit();

    float oacc[8][4];
#pragma unroll
    for (int ni = 0; ni < 8; ni++)
#pragma unroll
        for (int j = 0; j < 4; j++) oacc[ni][j] = 0.f;
    float mrun0 = -1e30f, mrun1 = -1e30f, lrun0 = 0.f, lrun1 = 0.f;
    uint32_t qf[4][4];

    for (int kb = 0; kb < 16; kb++) {
        cp_wait<1>();
        __syncthreads();
        if (kb + 2 < 16) issueKVB(kb + 2, (kb + 2) % 3);
        cp_commit();

        if (kb == 0) {
#pragma unroll
            for (int ks = 0; ks < 4; ks++)
                ldsm4(qf[ks], sb + swz(wrow + lrow, ks * 2 + lhi));
        }

        const int s = kb % 3;
        const uint32_t kbase = KBASE + s * 8192u;
        const uint32_t vbase = VBASE + s * 8192u;
        const uint32_t bbase = BBASE + s * 34816u;

        // ---- S = Q @ K^T (log2 domain) ----
        float sacc[8][4];
#pragma unroll
        for (int ni = 0; ni < 8; ni++)
#pragma unroll
            for (int j = 0; j < 4; j++) sacc[ni][j] = 0.f;
#pragma unroll
        for (int ks = 0; ks < 4; ks++) {
            uint32_t bf[4][4];
#pragma unroll
            for (int np = 0; np < 4; np++)
                ldsm4(bf[np], kbase + swz((np * 2 + lhi) * 8 + l8, ks * 2 + lg));
#pragma unroll
            for (int ni = 0; ni < 8; ni++)
                mma_f16(sacc[ni], qf[ks], &bf[ni >> 1][(ni & 1) * 2]);
        }

        // ---- bias add (from smem, conflict-free) ----
        {
            const uint32_t row0 = bbase + (uint32_t)(wrow + lq) * (BIAS_ROW * 4);
            const uint32_t row1 = row0 + 8u * (BIAS_ROW * 4);
#pragma unroll
            for (int ni = 0; ni < 8; ni++) {
                uint32_t co = (uint32_t)(ni * 8 + (lr << 1)) * 4u;
                float2 b0 = *(const float2*)(smem + (row0 + co - sb));
                float2 b1 = *(const float2*)(smem + (row1 + co - sb));
                sacc[ni][0] += BC * b0.x;
                sacc[ni][1] += BC * b0.y;
                sacc[ni][2] += BC * b1.x;
                sacc[ni][3] += BC * b1.y;
            }
        }

        // ---- online softmax (base-2) ----
        float mx0 = -1e30f, mx1 = -1e30f;
#pragma unroll
        for (int ni = 0; ni < 8; ni++) {
            mx0 = fmaxf(mx0, fmaxf(sacc[ni][0], sacc[ni][1]));
            mx1 = fmaxf(mx1, fmaxf(sacc[ni][2], sacc[ni][3]));
        }
        mx0 = fmaxf(mx0, __shfl_xor_sync(0xffffffffu, mx0, 1));
        mx0 = fmaxf(mx0, __shfl_xor_sync(0xffffffffu, mx0, 2));
        mx1 = fmaxf(mx1, __shfl_xor_sync(0xffffffffu, mx1, 1));
        mx1 = fmaxf(mx1, __shfl_xor_sync(0xffffffffu, mx1, 2));
        const float mn0 = fmaxf(mrun0, mx0), mn1 = fmaxf(mrun1, mx1);
        const float sc0 = ex2(mrun0 - mn0), sc1 = ex2(mrun1 - mn1);
        float sum0 = 0.f, sum1 = 0.f;
#pragma unroll
        for (int ni = 0; ni < 8; ni++) {
            sacc[ni][0] = ex2(sacc[ni][0] - mn0);
            sacc[ni][1] = ex2(sacc[ni][1] - mn0);
            sacc[ni][2] = ex2(sacc[ni][2] - mn1);
            sacc[ni][3] = ex2(sacc[ni][3] - mn1);
            sum0 += sacc[ni][0] + sacc[ni][1];
            sum1 += sacc[ni][2] + sacc[ni][3];
        }
        sum0 += __shfl_xor_sync(0xffffffffu, sum0, 1);
        sum0 += __shfl_xor_sync(0xffffffffu, sum0, 2);
        sum1 += __shfl_xor_sync(0xffffffffu, sum1, 1);
        sum1 += __shfl_xor_sync(0xffffffffu, sum1, 2);
        lrun0 = lrun0 * sc0 + sum0;
        lrun1 = lrun1 * sc1 + sum1;
        mrun0 = mn0; mrun1 = mn1;
#pragma unroll
        for (int ni = 0; ni < 8; ni++) {
            oacc[ni][0] *= sc0; oacc[ni][1] *= sc0;
            oacc[ni][2] *= sc1; oacc[ni][3] *= sc1;
        }

        // ---- P -> fp16 regs (C-frag == A-frag) ----
        uint32_t pl[8], pu[8];
#pragma unroll
        for (int ni = 0; ni < 8; ni++) {
            pl[ni] = h2u(__floats2half2_rn(sacc[ni][0], sacc[ni][1]));
            pu[ni] = h2u(__floats2half2_rn(sacc[ni][2], sacc[ni][3]));
        }

        // ---- O += P @ V (V via ldmatrix.trans) ----
#pragma unroll
        for (int ks = 0; ks < 4; ks++) {
            uint32_t a[4] = {pl[2 * ks], pu[2 * ks], pl[2 * ks + 1], pu[2 * ks + 1]};
            uint32_t bf[4][4];
#pragma unroll
            for (int np = 0; np < 4; np++)
                ldsm4t(bf[np], vbase + swz(ks * 16 + lg * 8 + l8, np * 2 + lhi));
#pragma unroll
            for (int ni = 0; ni < 8; ni++)
                mma_f16(oacc[ni], a, &bf[ni >> 1][(ni & 1) * 2]);
        }
    }

    // ---- epilogue: normalize + fp16 store ----
    const float inv0 = 1.0f / lrun0, inv1 = 1.0f / lrun1;
    __half* Op0 = Og + ((size_t)b * SEQ + (m0 + wrow + lq)) * EMB + h * HD;
    __half* Op1 = Op0 + (size_t)8 * EMB;
#pragma unroll
    for (int ni = 0; ni < 8; ni++) {
        int c = ni * 8 + (lr << 1);
        *(__half2*)(Op0 + c) = __floats2half2_rn(oacc[ni][0] * inv0, oacc[ni][1] * inv0);
        *(__half2*)(Op1 + c) = __floats2half2_rn(oacc[ni][2] * inv1, oacc[ni][3] * inv1);
    }
}

// ---------------- launcher ---------------------------------------------------
extern "C" void kernel_launch(void* const* d_in, const int* in_sizes, int n_in,
                              void* d_out, int out_size)
{
    const float* hidden = (const float*)d_in[0];
    const float* attn_b = (const float*)d_in[1];
    const float* Wq = (const float*)d_in[2];
    const float* bq = (const float*)d_in[3];
    const float* Wk = (const float*)d_in[4];
    const float* bk = (const float*)d_in[5];
    const float* Wv = (const float*)d_in[6];
    const float* bv = (const float*)d_in[7];
    const float* Wo = (const float*)d_in[8];
    const float* bo = (const float*)d_in[9];
    float* out = (float*)d_out;

    __half *h16, *w16, *q16, *k16, *v16, *a16;
    cudaGetSymbolAddress((void**)&h16, g_h16);
    cudaGetSymbolAddress((void**)&w16, g_w16);
    cudaGetSymbolAddress((void**)&q16, g_q16);
    cudaGetSymbolAddress((void**)&k16, g_k16);
    cudaGetSymbolAddress((void**)&v16, g_v16);
    cudaGetSymbolAddress((void**)&a16, g_a16);

    const int GEMM_SMEM = 147456;   // 3 x (16KB A + 32KB B)
    const int FLASH_SMEM = 65536 + 3 * 34816;   // 169984
    cudaFuncSetAttribute(hgemm<true>, cudaFuncAttributeMaxDynamicSharedMemorySize, GEMM_SMEM);
    cudaFuncSetAttribute(hgemm<false>, cudaFuncAttributeMaxDynamicSharedMemorySize, GEMM_SMEM);
    cudaFuncSetAttribute(flash16, cudaFuncAttributeMaxDynamicSharedMemorySize, FLASH_SMEM);

    // fused f32 -> fp16 conversions (single launch)
    conv_all<<<8192, 256>>>((const float4*)hidden, (const float4*)Wq,
                            (const float4*)Wk, (const float4*)Wv, (const float4*)Wo,
                            (uint2*)h16, (uint2*)w16);

    // QKV projections (fp16 out; q pre-scaled by SCALING*LOG2E for exp2 softmax)
    hgemm<true><<<dim3(EMB / 256, (BSZ * SEQ) / 128, 3), 256, GEMM_SMEM>>>(
        h16, w16, w16 + 1048576, w16 + 2 * 1048576,
        bq, bk, bv, q16, k16, v16, SCALING * LOG2E);

    // fused attention (fp16 in/out, async bias pipeline)
    flash16<<<dim3(SEQ / 128, BSZ * NH), 256, FLASH_SMEM>>>(q16, k16, v16, attn_b, a16);

    // output projection (f32 out)
    hgemm<false><<<dim3(EMB / 256, (BSZ * SEQ) / 128, 1), 256, GEMM_SMEM>>>(
        a16, w16 + 3 * 1048576, w16 + 3 * 1048576, w16 + 3 * 1048576,
        bo, bo, bo, out, out, out, 1.0f);
}